// round 6
// baseline (speedup 1.0000x reference)
#include <cuda_runtime.h>
#include <cstdint>
#include <math.h>

// Problem constants
#define Bb     16
#define Ss     384
#define Gg     384
#define NTOK   768
#define ECHAR  100
#define Dd     128
#define Tt     21
#define CSTART 19
#define CSTOP  20
#define BNROWS (Bb*NTOK)    // 12288
#define BSROWS (Bb*Ss)      // 6144

// scratch layout (floats) — 5,744,640 floats = 23.0 MB
#define OFF_XWHH   0u            // XW [2][6144][256] then reused as HH [4][12288][64]
#define OFF_GATIN  3145728u      // [12288][128]
#define OFF_H2     4718592u      // [12288][21]
#define OFF_LPROJ  4976640u
#define OFF_GOUT   5105664u      // [3][6144][21]
#define OFF_FEATS  5492736u
#define OFF_F1     5621760u
#define OFF_F2     5670912u
#define OFF_F1B    5720064u
#define OFF_F2B    5732352u
#define SCRATCH_TOTAL 5744640u

__device__ float g_scratch[SCRATCH_TOTAL];

// ---------------- gaz embedding gather ----------------
__global__ void embed_gaz_kernel(const int* __restrict__ gl,
                                 const float* __restrict__ tab) {
    int i = blockIdx.x * blockDim.x + threadIdx.x;
    if (i >= Bb * Gg * Dd) return;
    int r = i / Dd, f = i - r * Dd;
    int b = r / Gg, g = r - b * Gg;
    int idx = gl[r];
    if (idx < 0) idx = 0; if (idx >= 100000) idx = 99999;
    g_scratch[OFF_GATIN + ((size_t)b * NTOK + Ss + g) * Dd + f] =
        tab[(size_t)idx * Dd + f];
}

// ---------------- tiled fp32 GEMM (optional gathered-A) ----------------
__global__ __launch_bounds__(256)
void gemm_kernel(unsigned aoff, const float* __restrict__ Aext,
                 const int* __restrict__ gidx,
                 const float* __restrict__ Bm, const float* __restrict__ bias,
                 unsigned coff, int M, int N, int K, int transB,
                 int arpb, int astr) {
    float* C = g_scratch + coff;
    __shared__ float As[16][64];
    __shared__ float Bs[16][68];
    int tid = threadIdx.x;
    int tx = tid & 15, ty = tid >> 4;
    int rowBase = blockIdx.y * 64;
    int colBase = blockIdx.x * 64;
    float acc[4][4] = {};
    for (int k0 = 0; k0 < K; k0 += 16) {
        for (int l = tid; l < 1024; l += 256) {
            int r = l >> 4, kk = l & 15;
            int gr = rowBase + r, gk = k0 + kk;
            float v = 0.f;
            if (gr < M && gk < K) {
                if (gidx) {
                    int ci = gidx[gr];
                    if (ci < 0) ci = 0; if (ci >= 8000) ci = 7999;
                    v = Aext[(size_t)ci * K + gk];
                } else {
                    int sr = (gr / arpb) * astr + (gr % arpb);
                    v = g_scratch[aoff + (size_t)sr * K + gk];
                }
            }
            As[kk][r] = v;
        }
        for (int l = tid; l < 1024; l += 256) {
            int kk = l >> 6, c = l & 63;
            int gk = k0 + kk, gc = colBase + c;
            float v = 0.f;
            if (gk < K && gc < N)
                v = transB ? Bm[(size_t)gc * K + gk] : Bm[(size_t)gk * N + gc];
            Bs[kk][c] = v;
        }
        __syncthreads();
        #pragma unroll
        for (int kk = 0; kk < 16; kk++) {
            float a[4], b[4];
            #pragma unroll
            for (int i = 0; i < 4; i++) a[i] = As[kk][ty + 16 * i];
            #pragma unroll
            for (int j = 0; j < 4; j++) b[j] = Bs[kk][tx + 16 * j];
            #pragma unroll
            for (int i = 0; i < 4; i++)
                #pragma unroll
                for (int j = 0; j < 4; j++)
                    acc[i][j] += a[i] * b[j];
        }
        __syncthreads();
    }
    #pragma unroll
    for (int i = 0; i < 4; i++) {
        int row = rowBase + ty + 16 * i;
        if (row >= M) continue;
        #pragma unroll
        for (int j = 0; j < 4; j++) {
            int col = colBase + tx + 16 * j;
            if (col >= N) continue;
            float v = acc[i][j];
            if (bias) v += bias[col];
            C[(size_t)row * N + col] = v;
        }
    }
}

// ---------------- BiLSTM (one block per (batch, dir)) ----------------
__global__ __launch_bounds__(256)
void lstm_kernel(const float* __restrict__ whh_f, const float* __restrict__ whh_b) {
    int dir = blockIdx.x & 1, b = blockIdx.x >> 1;
    const float* whh = dir ? whh_b : whh_f;
    int g = threadIdx.x;
    float w[64];
    #pragma unroll
    for (int j = 0; j < 64; j++) w[j] = whh[g * 64 + j];
    __shared__ float hsh[64], csh[64], gates[256];
    if (g < 64) { hsh[g] = 0.f; csh[g] = 0.f; }
    __syncthreads();
    const float* xwd = g_scratch + OFF_XWHH + (size_t)dir * BSROWS * 256
                       + (size_t)b * Ss * 256;
    float* gat_in = g_scratch + OFF_GATIN;
    for (int step = 0; step < Ss; step++) {
        int t = dir ? (Ss - 1 - step) : step;
        float acc = xwd[(size_t)t * 256 + g];
        #pragma unroll
        for (int j = 0; j < 64; j++) acc += hsh[j] * w[j];
        gates[g] = acc;
        __syncthreads();
        if (g < 64) {
            float iv = 1.f / (1.f + expf(-gates[g]));
            float fv = 1.f / (1.f + expf(-gates[64 + g]));
            float gv = tanhf(gates[128 + g]);
            float ov = 1.f / (1.f + expf(-gates[192 + g]));
            float c = fv * csh[g] + iv * gv;
            csh[g] = c;
            float h = ov * tanhf(c);
            hsh[g] = h;
            gat_in[((size_t)b * NTOK + t) * Dd + dir * 64 + g] = h;
        }
        __syncthreads();
    }
}

// ---------------- f1/f2 for layer-1 heads ----------------
__global__ void f1f2_kernel(const float* __restrict__ avec) {
    const float* hfeat = g_scratch + OFF_XWHH;   // HH region
    int row = blockIdx.x;                        // 0..4*12288-1
    int tid = threadIdx.x;                       // 64
    const float* a = avec + (size_t)(row / BNROWS) * 128;
    float v = hfeat[(size_t)row * 64 + tid];
    float s1 = v * a[tid];
    float s2 = v * a[64 + tid];
    #pragma unroll
    for (int off = 16; off > 0; off >>= 1) {
        s1 += __shfl_down_sync(0xffffffffu, s1, off);
        s2 += __shfl_down_sync(0xffffffffu, s2, off);
    }
    __shared__ float sh[4];
    if ((tid & 31) == 0) { sh[(tid >> 5) * 2] = s1; sh[(tid >> 5) * 2 + 1] = s2; }
    __syncthreads();
    if (tid == 0) {
        g_scratch[OFF_F1 + row] = sh[0] + sh[2];
        g_scratch[OFF_F2 + row] = sh[1] + sh[3];
    }
}

// ---------------- fused GAT layer-1 attn + layer-2 projection ----------------
__global__ __launch_bounds__(256)
void attn1_kernel(const int* __restrict__ adj, const float* __restrict__ Wo,
                  const float* __restrict__ ao) {
    const float* f1 = g_scratch + OFF_F1;
    const float* f2 = g_scratch + OFF_F2;
    const float* hh = g_scratch + OFF_XWHH;
    int b = blockIdx.y, i = blockIdx.x;
    int tid = threadIdx.x;
    __shared__ int jl[768];
    __shared__ int cnts[256];
    __shared__ float psm[4 * 768];
    __shared__ float f2s[4 * 768];
    __shared__ float wred[4][8];
    __shared__ float gmax[4], gsum[4];
    __shared__ float hrow[256];
    __shared__ float h2s[21];

    for (int l = tid; l < 4 * 768; l += 256) {
        int m = l / 768;
        int jj = l - m * 768;
        f2s[l] = f2[(size_t)m * BNROWS + (size_t)b * 768 + jj];
    }

    const int* arow = adj + ((size_t)b * 768 + i) * 768;
    int local[3]; int c = 0;
    #pragma unroll
    for (int q = 0; q < 3; q++) {
        int j = tid * 3 + q;
        if (arow[j] > 0) local[c++] = j;
    }
    cnts[tid] = c;
    __syncthreads();
    for (int off = 1; off < 256; off <<= 1) {
        int v = cnts[tid];
        if (tid >= off) v += cnts[tid - off];
        __syncthreads();
        cnts[tid] = v;
        __syncthreads();
    }
    int start = cnts[tid] - c;
    int nnz = cnts[255];
    for (int q = 0; q < c; q++) jl[start + q] = local[q];
    __syncthreads();

    float f1v[4];
    #pragma unroll
    for (int m = 0; m < 4; m++)
        f1v[m] = f1[(size_t)m * BNROWS + (size_t)b * 768 + i];
    float lmax[4] = {-3e38f, -3e38f, -3e38f, -3e38f};
    for (int idx = tid; idx < nnz; idx += 256) {
        int j = jl[idx];
        #pragma unroll
        for (int m = 0; m < 4; m++) {
            float e = f1v[m] + f2s[m * 768 + j];
            e = e > 0.f ? e : 0.2f * e;
            psm[m * 768 + idx] = e;
            lmax[m] = fmaxf(lmax[m], e);
        }
    }
    int lane = tid & 31, warp = tid >> 5;
    #pragma unroll
    for (int m = 0; m < 4; m++) {
        float v = lmax[m];
        #pragma unroll
        for (int off = 16; off > 0; off >>= 1)
            v = fmaxf(v, __shfl_down_sync(0xffffffffu, v, off));
        if (lane == 0) wred[m][warp] = v;
    }
    __syncthreads();
    if (tid < 4) {
        float mm = -3e38f;
        for (int w = 0; w < 8; w++) mm = fmaxf(mm, wred[tid][w]);
        gmax[tid] = mm;
    }
    __syncthreads();

    float lsum[4] = {0.f, 0.f, 0.f, 0.f};
    for (int idx = tid; idx < nnz; idx += 256) {
        #pragma unroll
        for (int m = 0; m < 4; m++) {
            float v = expf(psm[m * 768 + idx] - gmax[m]);
            psm[m * 768 + idx] = v;
            lsum[m] += v;
        }
    }
    #pragma unroll
    for (int m = 0; m < 4; m++) {
        float v = lsum[m];
        #pragma unroll
        for (int off = 16; off > 0; off >>= 1)
            v += __shfl_down_sync(0xffffffffu, v, off);
        if (lane == 0) wred[m][warp] = v;
    }
    __syncthreads();
    if (tid < 4) {
        float ss = 0.f;
        for (int w = 0; w < 8; w++) ss += wred[tid][w];
        gsum[tid] = ss;
    }
    __syncthreads();

    // per-head aggregate + ELU -> hrow[256] (hcat layout: head-major)
    {
        int m = tid >> 6, f = tid & 63;
        const float* hp = hh + ((size_t)m * BNROWS + (size_t)b * 768) * 64 + f;
        float acc = 0.f;
        #pragma unroll 4
        for (int idx = 0; idx < nnz; idx++)
            acc += psm[m * 768 + idx] * hp[(size_t)jl[idx] * 64];
        float denom = gsum[m];
        acc = (denom > 0.f) ? acc / denom : 0.f;
        acc = acc > 0.f ? acc : expm1f(acc);
        hrow[tid] = acc;
    }
    __syncthreads();

    // layer-2 projection h2 = hrow @ Wo
    if (tid < 21) {
        float acc = 0.f;
        #pragma unroll 8
        for (int cix = 0; cix < 256; cix++)
            acc += hrow[cix] * Wo[cix * 21 + tid];
        g_scratch[OFF_H2 + ((size_t)b * 768 + i) * 21 + tid] = acc;
        h2s[tid] = acc;
    }
    __syncthreads();
    if (tid < 2) {
        const float* av = ao + tid * 21;
        float s = 0.f;
        for (int t = 0; t < 21; t++) s += h2s[t] * av[t];
        g_scratch[(tid == 0 ? OFF_F1B : OFF_F2B) + (size_t)b * 768 + i] = s;
    }
}

// ---------------- GAT layer-2 sparse attention (1 head, F=21) ----------------
__global__ __launch_bounds__(256)
void attn2_kernel(const int* __restrict__ adj, unsigned outoff) {
    const float* f1 = g_scratch + OFF_F1B;
    const float* f2 = g_scratch + OFF_F2B;
    const float* h2 = g_scratch + OFF_H2;
    int b = blockIdx.y, i = blockIdx.x;  // i < Ss
    int tid = threadIdx.x;
    __shared__ int jl[768];
    __shared__ int cnts[256];
    __shared__ float psm[768];
    __shared__ float f2s[768];
    __shared__ float wred[8];
    __shared__ float gmax1, gsum1;

    for (int l = tid; l < 768; l += 256)
        f2s[l] = f2[(size_t)b * 768 + l];

    const int* arow = adj + ((size_t)b * 768 + i) * 768;
    int local[3]; int c = 0;
    #pragma unroll
    for (int q = 0; q < 3; q++) {
        int j = tid * 3 + q;
        if (arow[j] > 0) local[c++] = j;
    }
    cnts[tid] = c;
    __syncthreads();
    for (int off = 1; off < 256; off <<= 1) {
        int v = cnts[tid];
        if (tid >= off) v += cnts[tid - off];
        __syncthreads();
        cnts[tid] = v;
        __syncthreads();
    }
    int start = cnts[tid] - c;
    int nnz = cnts[255];
    for (int q = 0; q < c; q++) jl[start + q] = local[q];
    __syncthreads();

    float f1v = f1[(size_t)b * 768 + i];
    float lmax = -3e38f;
    for (int idx = tid; idx < nnz; idx += 256) {
        float e = f1v + f2s[jl[idx]];
        e = e > 0.f ? e : 0.2f * e;
        psm[idx] = e;
        lmax = fmaxf(lmax, e);
    }
    int lane = tid & 31, warp = tid >> 5;
    #pragma unroll
    for (int off = 16; off > 0; off >>= 1)
        lmax = fmaxf(lmax, __shfl_down_sync(0xffffffffu, lmax, off));
    if (lane == 0) wred[warp] = lmax;
    __syncthreads();
    if (tid == 0) {
        float mm = -3e38f;
        for (int w = 0; w < 8; w++) mm = fmaxf(mm, wred[w]);
        gmax1 = mm;
    }
    __syncthreads();

    float lsum = 0.f;
    for (int idx = tid; idx < nnz; idx += 256) {
        float v = expf(psm[idx] - gmax1);
        psm[idx] = v;
        lsum += v;
    }
    #pragma unroll
    for (int off = 16; off > 0; off >>= 1)
        lsum += __shfl_down_sync(0xffffffffu, lsum, off);
    if (lane == 0) wred[warp] = lsum;
    __syncthreads();
    if (tid == 0) {
        float ss = 0.f;
        for (int w = 0; w < 8; w++) ss += wred[w];
        gsum1 = ss;
    }
    __syncthreads();

    if (tid < 21) {
        const float* hp = h2 + (size_t)b * 768 * 21 + tid;
        float acc = 0.f;
        #pragma unroll 4
        for (int idx = 0; idx < nnz; idx++)
            acc += psm[idx] * hp[(size_t)jl[idx] * 21];
        float denom = gsum1;
        acc = (denom > 0.f) ? acc / denom : 0.f;
        acc = acc > 0.f ? acc : expm1f(acc);
        g_scratch[outoff + ((size_t)b * Ss + i) * 21 + tid] = acc;
    }
}

// ---------------- fuse ----------------
__global__ void fuse_kernel(const float* __restrict__ fw) {
    int i = blockIdx.x * blockDim.x + threadIdx.x;
    if (i >= Bb * Ss * Tt) return;
    const float* lproj = g_scratch + OFF_LPROJ;
    const float* g0 = g_scratch + OFF_GOUT;
    const float* g1 = g0 + BSROWS * Tt;
    const float* g2 = g1 + BSROWS * Tt;
    g_scratch[OFF_FEATS + i] =
        fw[0] * lproj[i] + fw[1] * g0[i] + fw[2] * g1[i] + fw[3] * g2[i];
}

// ---------------- Viterbi (FLOAT32 output!) ----------------
__global__ __launch_bounds__(32)
void viterbi_kernel(const float* __restrict__ trans,
                    const int* __restrict__ mask, float* __restrict__ outv) {
    const float* feats = g_scratch + OFF_FEATS;
    int b = blockIdx.x;
    int tid = threadIdx.x;
    __shared__ float part[21], np[21];
    __shared__ float trsh[441];
    __shared__ short bps[Ss * Tt];
    __shared__ int tags[Ss];
    for (int l = tid; l < 441; l += 32) trsh[l] = trans[l];
    __syncthreads();
    if (tid < 21)
        part[tid] = feats[((size_t)b * Ss) * Tt + tid] + trsh[CSTART * 21 + tid];
    __syncthreads();
    for (int t = 1; t < Ss; t++) {
        if (tid < 21) {
            float ft = feats[((size_t)b * Ss + t) * Tt + tid];
            float best = -3e38f; int bi = 0;
            #pragma unroll
            for (int p = 0; p < 21; p++) {
                float v = part[p] + trsh[p * 21 + tid] + ft;
                if (v > best) { best = v; bi = p; }
            }
            int m = mask[b * Ss + t];
            np[tid] = (m > 0) ? best : part[tid];
            bps[t * Tt + tid] = (short)((m > 0) ? bi : tid);
        }
        __syncthreads();
        if (tid < 21) part[tid] = np[tid];
        __syncthreads();
    }
    if (tid == 0) {
        float best = -3e38f; int bt = 0;
        for (int p = 0; p < 21; p++) {
            float v = part[p] + trsh[p * 21 + CSTOP];
            if (v > best) { best = v; bt = p; }
        }
        tags[Ss - 1] = bt;
        int tag = bt;
        for (int t = Ss - 1; t >= 1; t--) {
            tag = (int)bps[t * Tt + tag];
            tags[t - 1] = tag;
        }
    }
    __syncthreads();
    for (int t = tid; t < Ss; t += 32)
        outv[(size_t)b * Ss + t] = (float)tags[t];
}

// ---------------- launch ----------------
extern "C" void kernel_launch(void* const* d_in, const int* in_sizes, int n_in,
                              void* d_out, int out_size) {
    const int*   batch_char = (const int*)d_in[0];
    const int*   gaz_list   = (const int*)d_in[2];
    const int*   graphs[3]  = {(const int*)d_in[3], (const int*)d_in[4], (const int*)d_in[5]};
    const int*   mask       = (const int*)d_in[6];
    const float* char_table = (const float*)d_in[7];
    const float* gaz_table  = (const float*)d_in[8];
    const float* w_ih_f     = (const float*)d_in[9];
    const float* w_hh_f     = (const float*)d_in[10];
    const float* b_f        = (const float*)d_in[11];
    const float* w_ih_b     = (const float*)d_in[12];
    const float* w_hh_b     = (const float*)d_in[13];
    const float* b_b        = (const float*)d_in[14];
    const float* h2h_W      = (const float*)d_in[15];
    const float* h2h_b      = (const float*)d_in[16];
    const float* gat_Wh     = (const float*)d_in[17];
    const float* gat_ah     = (const float*)d_in[18];
    const float* gat_Wo     = (const float*)d_in[19];
    const float* gat_ao     = (const float*)d_in[20];
    const float* fuse_w     = (const float*)d_in[21];
    const float* trans      = (const float*)d_in[22];

    // xw = emb @ W_ih^T + b  (char-embedding gather fused into A-load)
    {
        dim3 grid(4, 96);
        gemm_kernel<<<grid, 256>>>(0, char_table, batch_char, w_ih_f, b_f,
                                   OFF_XWHH, BSROWS, 256, ECHAR, 1, 1, 1);
        gemm_kernel<<<grid, 256>>>(0, char_table, batch_char, w_ih_b, b_b,
                                   OFF_XWHH + BSROWS * 256, BSROWS, 256, ECHAR, 1, 1, 1);
    }
    embed_gaz_kernel<<<(Bb * Gg * Dd + 255) / 256, 256>>>(gaz_list, gaz_table);
    lstm_kernel<<<32, 256>>>(w_hh_f, w_hh_b);

    // lstm projection (lstm rows strided within gatin)
    gemm_kernel<<<dim3(1, 96), 256>>>(OFF_GATIN, nullptr, nullptr, h2h_W, h2h_b,
                                      OFF_LPROJ, BSROWS, Tt, Dd, 1, Ss, NTOK);

    for (int k = 0; k < 3; k++) {
        for (int m = 0; m < 4; m++)
            gemm_kernel<<<dim3(1, 192), 256>>>(
                OFF_GATIN, nullptr, nullptr,
                gat_Wh + ((size_t)(k * 4 + m)) * Dd * 64, nullptr,
                OFF_XWHH + (unsigned)m * BNROWS * 64,
                BNROWS, 64, Dd, 0, BNROWS, BNROWS);
        f1f2_kernel<<<4 * BNROWS, 64>>>(gat_ah + (size_t)k * 4 * 128);
        attn1_kernel<<<dim3(NTOK, Bb), 256>>>(graphs[k],
                                              gat_Wo + (size_t)k * 256 * Tt,
                                              gat_ao + (size_t)k * 2 * Tt);
        attn2_kernel<<<dim3(Ss, Bb), 256>>>(graphs[k],
                                            OFF_GOUT + (unsigned)k * BSROWS * Tt);
    }

    fuse_kernel<<<(Bb * Ss * Tt + 255) / 256, 256>>>(fuse_w);
    viterbi_kernel<<<Bb, 32>>>(trans, mask, (float*)d_out);
}

// round 7
// speedup vs baseline: 1.3177x; 1.3177x over previous
#include <cuda_runtime.h>
#include <cstdint>
#include <math.h>

// Problem constants
#define Bb     16
#define Ss     384
#define Gg     384
#define NTOK   768
#define ECHAR  100
#define Dd     128
#define Tt     21
#define CSTART 19
#define CSTOP  20
#define BNROWS (Bb*NTOK)    // 12288
#define BSROWS (Bb*Ss)      // 6144

// scratch layout (floats) — 5,744,640 floats = 23.0 MB
#define OFF_XWHH   0u            // XW [2][6144][256] then reused as HH [4][12288][64]
#define OFF_GATIN  3145728u      // [12288][128]
#define OFF_H2     4718592u      // [12288][21]
#define OFF_LPROJ  4976640u
#define OFF_GOUT   5105664u      // [3][6144][21]
#define OFF_FEATS  5492736u
#define OFF_F1     5621760u
#define OFF_F2     5670912u
#define OFF_F1B    5720064u
#define OFF_F2B    5732352u
#define SCRATCH_TOTAL 5744640u

__device__ float g_scratch[SCRATCH_TOTAL];

// ---------------- gaz embedding gather ----------------
__global__ void embed_gaz_kernel(const int* __restrict__ gl,
                                 const float* __restrict__ tab) {
    int i = blockIdx.x * blockDim.x + threadIdx.x;
    if (i >= Bb * Gg * Dd) return;
    int r = i / Dd, f = i - r * Dd;
    int b = r / Gg, g = r - b * Gg;
    int idx = gl[r];
    if (idx < 0) idx = 0; if (idx >= 100000) idx = 99999;
    g_scratch[OFF_GATIN + ((size_t)b * NTOK + Ss + g) * Dd + f] =
        tab[(size_t)idx * Dd + f];
}

// ---------------- generic tiled fp32 GEMM (optional gathered-A) ----------------
__global__ __launch_bounds__(256)
void gemm_kernel(unsigned aoff, const float* __restrict__ Aext,
                 const int* __restrict__ gidx,
                 const float* __restrict__ Bm, const float* __restrict__ bias,
                 unsigned coff, int M, int N, int K, int transB,
                 int arpb, int astr) {
    float* C = g_scratch + coff;
    __shared__ float As[16][64];
    __shared__ float Bs[16][68];
    int tid = threadIdx.x;
    int tx = tid & 15, ty = tid >> 4;
    int rowBase = blockIdx.y * 64;
    int colBase = blockIdx.x * 64;
    float acc[4][4] = {};
    for (int k0 = 0; k0 < K; k0 += 16) {
        for (int l = tid; l < 1024; l += 256) {
            int r = l >> 4, kk = l & 15;
            int gr = rowBase + r, gk = k0 + kk;
            float v = 0.f;
            if (gr < M && gk < K) {
                if (gidx) {
                    int ci = gidx[gr];
                    if (ci < 0) ci = 0; if (ci >= 8000) ci = 7999;
                    v = Aext[(size_t)ci * K + gk];
                } else {
                    int sr = (gr / arpb) * astr + (gr % arpb);
                    v = g_scratch[aoff + (size_t)sr * K + gk];
                }
            }
            As[kk][r] = v;
        }
        for (int l = tid; l < 1024; l += 256) {
            int kk = l >> 6, c = l & 63;
            int gk = k0 + kk, gc = colBase + c;
            float v = 0.f;
            if (gk < K && gc < N)
                v = transB ? Bm[(size_t)gc * K + gk] : Bm[(size_t)gk * N + gc];
            Bs[kk][c] = v;
        }
        __syncthreads();
        #pragma unroll
        for (int kk = 0; kk < 16; kk++) {
            float a[4], b[4];
            #pragma unroll
            for (int i = 0; i < 4; i++) a[i] = As[kk][ty + 16 * i];
            #pragma unroll
            for (int j = 0; j < 4; j++) b[j] = Bs[kk][tx + 16 * j];
            #pragma unroll
            for (int i = 0; i < 4; i++)
                #pragma unroll
                for (int j = 0; j < 4; j++)
                    acc[i][j] += a[i] * b[j];
        }
        __syncthreads();
    }
    #pragma unroll
    for (int i = 0; i < 4; i++) {
        int row = rowBase + ty + 16 * i;
        if (row >= M) continue;
        #pragma unroll
        for (int j = 0; j < 4; j++) {
            int col = colBase + tx + 16 * j;
            if (col >= N) continue;
            float v = acc[i][j];
            if (bias) v += bias[col];
            C[(size_t)row * N + col] = v;
        }
    }
}

// ---------------- head-projection GEMM with fused f1/f2 epilogue ----------------
// grid (4 heads, 192 row-tiles). A = gatin [12288][128], B = Wh[m] [128][64].
// C = HH[m][12288][64]; epilogue writes f1/f2 (row · a1, row · a2).
__global__ __launch_bounds__(256)
void gemm_heads_kernel(const float* __restrict__ Wh, const float* __restrict__ ah) {
    int m = blockIdx.x;
    int rowBase = blockIdx.y * 64;
    const float* A = g_scratch + OFF_GATIN;
    const float* B = Wh + (size_t)m * (Dd * 64);
    float* C = g_scratch + OFF_XWHH + (size_t)m * BNROWS * 64;
    __shared__ float As[16][64];
    __shared__ float Bs[16][68];
    int tid = threadIdx.x;
    int tx = tid & 15, ty = tid >> 4;
    float acc[4][4] = {};
    for (int k0 = 0; k0 < Dd; k0 += 16) {
        for (int l = tid; l < 1024; l += 256) {
            int r = l >> 4, kk = l & 15;
            As[kk][r] = A[(size_t)(rowBase + r) * Dd + k0 + kk];
        }
        for (int l = tid; l < 1024; l += 256) {
            int kk = l >> 6, c = l & 63;
            Bs[kk][c] = B[(size_t)(k0 + kk) * 64 + c];
        }
        __syncthreads();
        #pragma unroll
        for (int kk = 0; kk < 16; kk++) {
            float a[4], b[4];
            #pragma unroll
            for (int i = 0; i < 4; i++) a[i] = As[kk][ty + 16 * i];
            #pragma unroll
            for (int j = 0; j < 4; j++) b[j] = Bs[kk][tx + 16 * j];
            #pragma unroll
            for (int i = 0; i < 4; i++)
                #pragma unroll
                for (int j = 0; j < 4; j++)
                    acc[i][j] += a[i] * b[j];
        }
        __syncthreads();
    }
    const float* a1 = ah + (size_t)m * 128;
    float av1[4], av2[4];
    #pragma unroll
    for (int j = 0; j < 4; j++) {
        av1[j] = a1[tx + 16 * j];
        av2[j] = a1[64 + tx + 16 * j];
    }
    #pragma unroll
    for (int i = 0; i < 4; i++) {
        int row = rowBase + ty + 16 * i;
        float p1 = 0.f, p2 = 0.f;
        #pragma unroll
        for (int j = 0; j < 4; j++) {
            float v = acc[i][j];
            C[(size_t)row * 64 + tx + 16 * j] = v;
            p1 += v * av1[j];
            p2 += v * av2[j];
        }
        #pragma unroll
        for (int off = 8; off > 0; off >>= 1) {
            p1 += __shfl_xor_sync(0xffffffffu, p1, off);
            p2 += __shfl_xor_sync(0xffffffffu, p2, off);
        }
        if (tx == 0) {
            g_scratch[OFF_F1 + (size_t)m * BNROWS + row] = p1;
            g_scratch[OFF_F2 + (size_t)m * BNROWS + row] = p2;
        }
    }
}

// ---------------- BiLSTM (prefetched, float4 h loads, c in register) ----------------
__global__ __launch_bounds__(256)
void lstm_kernel(const float* __restrict__ whh_f, const float* __restrict__ whh_b) {
    int dir = blockIdx.x & 1, b = blockIdx.x >> 1;
    const float* whh = dir ? whh_b : whh_f;
    int g = threadIdx.x;
    float w[64];
    #pragma unroll
    for (int j = 0; j < 64; j++) w[j] = whh[g * 64 + j];
    __shared__ __align__(16) float hsh[64];
    __shared__ float gates[256];
    float creg = 0.f;
    if (g < 64) hsh[g] = 0.f;
    __syncthreads();
    const float* xwd = g_scratch + OFF_XWHH + (size_t)dir * BSROWS * 256
                       + (size_t)b * Ss * 256;
    float* gat_in = g_scratch + OFF_GATIN;
    int t = dir ? (Ss - 1) : 0;
    int dt = dir ? -1 : 1;
    float xnext = xwd[(size_t)t * 256 + g];
    for (int step = 0; step < Ss; step++, t += dt) {
        float acc = xnext;
        if (step + 1 < Ss) xnext = xwd[(size_t)(t + dt) * 256 + g];  // prefetch
        const float4* h4 = (const float4*)hsh;
        #pragma unroll
        for (int j4 = 0; j4 < 16; j4++) {
            float4 hv = h4[j4];
            acc += hv.x * w[4 * j4] + hv.y * w[4 * j4 + 1]
                 + hv.z * w[4 * j4 + 2] + hv.w * w[4 * j4 + 3];
        }
        gates[g] = acc;
        __syncthreads();
        if (g < 64) {
            float iv = 1.f / (1.f + expf(-gates[g]));
            float fv = 1.f / (1.f + expf(-gates[64 + g]));
            float gv = tanhf(gates[128 + g]);
            float ov = 1.f / (1.f + expf(-gates[192 + g]));
            creg = fv * creg + iv * gv;
            float h = ov * tanhf(creg);
            hsh[g] = h;
            gat_in[((size_t)b * NTOK + t) * Dd + dir * 64 + g] = h;
        }
        __syncthreads();
    }
}

// ---------------- fused GAT layer-1 attn + layer-2 projection ----------------
__global__ __launch_bounds__(256)
void attn1_kernel(const int* __restrict__ adj, const float* __restrict__ Wo,
                  const float* __restrict__ ao) {
    const float* f1 = g_scratch + OFF_F1;
    const float* f2 = g_scratch + OFF_F2;
    const float* hh = g_scratch + OFF_XWHH;
    int b = blockIdx.y, i = blockIdx.x;
    int tid = threadIdx.x;
    __shared__ int jl[768];
    __shared__ int cnts[256];
    __shared__ float psm[4 * 768];
    __shared__ float f2s[4 * 768];
    __shared__ float wred[4][8];
    __shared__ float gmax[4], gsum[4];
    __shared__ float hrow[256];
    __shared__ float h2s[21];

    for (int l = tid; l < 4 * 768; l += 256) {
        int m = l / 768;
        int jj = l - m * 768;
        f2s[l] = f2[(size_t)m * BNROWS + (size_t)b * 768 + jj];
    }

    const int* arow = adj + ((size_t)b * 768 + i) * 768;
    int local[3]; int c = 0;
    #pragma unroll
    for (int q = 0; q < 3; q++) {
        int j = tid * 3 + q;
        if (arow[j] > 0) local[c++] = j;
    }
    cnts[tid] = c;
    __syncthreads();
    for (int off = 1; off < 256; off <<= 1) {
        int v = cnts[tid];
        if (tid >= off) v += cnts[tid - off];
        __syncthreads();
        cnts[tid] = v;
        __syncthreads();
    }
    int start = cnts[tid] - c;
    int nnz = cnts[255];
    for (int q = 0; q < c; q++) jl[start + q] = local[q];
    __syncthreads();

    float f1v[4];
    #pragma unroll
    for (int m = 0; m < 4; m++)
        f1v[m] = f1[(size_t)m * BNROWS + (size_t)b * 768 + i];
    float lmax[4] = {-3e38f, -3e38f, -3e38f, -3e38f};
    for (int idx = tid; idx < nnz; idx += 256) {
        int j = jl[idx];
        #pragma unroll
        for (int m = 0; m < 4; m++) {
            float e = f1v[m] + f2s[m * 768 + j];
            e = e > 0.f ? e : 0.2f * e;
            psm[m * 768 + idx] = e;
            lmax[m] = fmaxf(lmax[m], e);
        }
    }
    int lane = tid & 31, warp = tid >> 5;
    #pragma unroll
    for (int m = 0; m < 4; m++) {
        float v = lmax[m];
        #pragma unroll
        for (int off = 16; off > 0; off >>= 1)
            v = fmaxf(v, __shfl_down_sync(0xffffffffu, v, off));
        if (lane == 0) wred[m][warp] = v;
    }
    __syncthreads();
    if (tid < 4) {
        float mm = -3e38f;
        for (int w = 0; w < 8; w++) mm = fmaxf(mm, wred[tid][w]);
        gmax[tid] = mm;
    }
    __syncthreads();

    float lsum[4] = {0.f, 0.f, 0.f, 0.f};
    for (int idx = tid; idx < nnz; idx += 256) {
        #pragma unroll
        for (int m = 0; m < 4; m++) {
            float v = expf(psm[m * 768 + idx] - gmax[m]);
            psm[m * 768 + idx] = v;
            lsum[m] += v;
        }
    }
    #pragma unroll
    for (int m = 0; m < 4; m++) {
        float v = lsum[m];
        #pragma unroll
        for (int off = 16; off > 0; off >>= 1)
            v += __shfl_down_sync(0xffffffffu, v, off);
        if (lane == 0) wred[m][warp] = v;
    }
    __syncthreads();
    if (tid < 4) {
        float ss = 0.f;
        for (int w = 0; w < 8; w++) ss += wred[tid][w];
        gsum[tid] = ss;
    }
    __syncthreads();

    // per-head aggregate + ELU -> hrow[256] (head-major layout)
    {
        int m = tid >> 6, f = tid & 63;
        const float* hp = hh + ((size_t)m * BNROWS + (size_t)b * 768) * 64 + f;
        float acc = 0.f;
        #pragma unroll 4
        for (int idx = 0; idx < nnz; idx++)
            acc += psm[m * 768 + idx] * hp[(size_t)jl[idx] * 64];
        float denom = gsum[m];
        acc = (denom > 0.f) ? acc / denom : 0.f;
        acc = acc > 0.f ? acc : expm1f(acc);
        hrow[tid] = acc;
    }
    __syncthreads();

    // layer-2 projection h2 = hrow @ Wo
    if (tid < 21) {
        float acc = 0.f;
        #pragma unroll 8
        for (int cix = 0; cix < 256; cix++)
            acc += hrow[cix] * Wo[cix * 21 + tid];
        g_scratch[OFF_H2 + ((size_t)b * 768 + i) * 21 + tid] = acc;
        h2s[tid] = acc;
    }
    __syncthreads();
    if (tid < 2) {
        const float* av = ao + tid * 21;
        float s = 0.f;
        for (int t = 0; t < 21; t++) s += h2s[t] * av[t];
        g_scratch[(tid == 0 ? OFF_F1B : OFF_F2B) + (size_t)b * 768 + i] = s;
    }
}

// ---------------- GAT layer-2 sparse attention (1 head, F=21) ----------------
__global__ __launch_bounds__(256)
void attn2_kernel(const int* __restrict__ adj, unsigned outoff) {
    const float* f1 = g_scratch + OFF_F1B;
    const float* f2 = g_scratch + OFF_F2B;
    const float* h2 = g_scratch + OFF_H2;
    int b = blockIdx.y, i = blockIdx.x;  // i < Ss
    int tid = threadIdx.x;
    __shared__ int jl[768];
    __shared__ int cnts[256];
    __shared__ float psm[768];
    __shared__ float f2s[768];
    __shared__ float wred[8];
    __shared__ float gmax1, gsum1;

    for (int l = tid; l < 768; l += 256)
        f2s[l] = f2[(size_t)b * 768 + l];

    const int* arow = adj + ((size_t)b * 768 + i) * 768;
    int local[3]; int c = 0;
    #pragma unroll
    for (int q = 0; q < 3; q++) {
        int j = tid * 3 + q;
        if (arow[j] > 0) local[c++] = j;
    }
    cnts[tid] = c;
    __syncthreads();
    for (int off = 1; off < 256; off <<= 1) {
        int v = cnts[tid];
        if (tid >= off) v += cnts[tid - off];
        __syncthreads();
        cnts[tid] = v;
        __syncthreads();
    }
    int start = cnts[tid] - c;
    int nnz = cnts[255];
    for (int q = 0; q < c; q++) jl[start + q] = local[q];
    __syncthreads();

    float f1v = f1[(size_t)b * 768 + i];
    float lmax = -3e38f;
    for (int idx = tid; idx < nnz; idx += 256) {
        float e = f1v + f2s[jl[idx]];
        e = e > 0.f ? e : 0.2f * e;
        psm[idx] = e;
        lmax = fmaxf(lmax, e);
    }
    int lane = tid & 31, warp = tid >> 5;
    #pragma unroll
    for (int off = 16; off > 0; off >>= 1)
        lmax = fmaxf(lmax, __shfl_down_sync(0xffffffffu, lmax, off));
    if (lane == 0) wred[warp] = lmax;
    __syncthreads();
    if (tid == 0) {
        float mm = -3e38f;
        for (int w = 0; w < 8; w++) mm = fmaxf(mm, wred[w]);
        gmax1 = mm;
    }
    __syncthreads();

    float lsum = 0.f;
    for (int idx = tid; idx < nnz; idx += 256) {
        float v = expf(psm[idx] - gmax1);
        psm[idx] = v;
        lsum += v;
    }
    #pragma unroll
    for (int off = 16; off > 0; off >>= 1)
        lsum += __shfl_down_sync(0xffffffffu, lsum, off);
    if (lane == 0) wred[warp] = lsum;
    __syncthreads();
    if (tid == 0) {
        float ss = 0.f;
        for (int w = 0; w < 8; w++) ss += wred[w];
        gsum1 = ss;
    }
    __syncthreads();

    if (tid < 21) {
        const float* hp = h2 + (size_t)b * 768 * 21 + tid;
        float acc = 0.f;
        #pragma unroll 4
        for (int idx = 0; idx < nnz; idx++)
            acc += psm[idx] * hp[(size_t)jl[idx] * 21];
        float denom = gsum1;
        acc = (denom > 0.f) ? acc / denom : 0.f;
        acc = acc > 0.f ? acc : expm1f(acc);
        g_scratch[outoff + ((size_t)b * Ss + i) * 21 + tid] = acc;
    }
}

// ---------------- fuse ----------------
__global__ void fuse_kernel(const float* __restrict__ fw) {
    int i = blockIdx.x * blockDim.x + threadIdx.x;
    if (i >= Bb * Ss * Tt) return;
    const float* lproj = g_scratch + OFF_LPROJ;
    const float* g0 = g_scratch + OFF_GOUT;
    const float* g1 = g0 + BSROWS * Tt;
    const float* g2 = g1 + BSROWS * Tt;
    g_scratch[OFF_FEATS + i] =
        fw[0] * lproj[i] + fw[1] * g0[i] + fw[2] * g1[i] + fw[3] * g2[i];
}

// ---------------- Viterbi (float32 output) ----------------
__global__ __launch_bounds__(32)
void viterbi_kernel(const float* __restrict__ trans,
                    const int* __restrict__ mask, float* __restrict__ outv) {
    const float* feats = g_scratch + OFF_FEATS;
    int b = blockIdx.x;
    int tid = threadIdx.x;
    __shared__ float part[21], np[21];
    __shared__ float trsh[441];
    __shared__ short bps[Ss * Tt];
    __shared__ int tags[Ss];
    for (int l = tid; l < 441; l += 32) trsh[l] = trans[l];
    __syncthreads();
    if (tid < 21)
        part[tid] = feats[((size_t)b * Ss) * Tt + tid] + trsh[CSTART * 21 + tid];
    __syncthreads();
    for (int t = 1; t < Ss; t++) {
        if (tid < 21) {
            float ft = feats[((size_t)b * Ss + t) * Tt + tid];
            float best = -3e38f; int bi = 0;
            #pragma unroll
            for (int p = 0; p < 21; p++) {
                float v = part[p] + trsh[p * 21 + tid] + ft;
                if (v > best) { best = v; bi = p; }
            }
            int m = mask[b * Ss + t];
            np[tid] = (m > 0) ? best : part[tid];
            bps[t * Tt + tid] = (short)((m > 0) ? bi : tid);
        }
        __syncthreads();
        if (tid < 21) part[tid] = np[tid];
        __syncthreads();
    }
    if (tid == 0) {
        float best = -3e38f; int bt = 0;
        for (int p = 0; p < 21; p++) {
            float v = part[p] + trsh[p * 21 + CSTOP];
            if (v > best) { best = v; bt = p; }
        }
        tags[Ss - 1] = bt;
        int tag = bt;
        for (int t = Ss - 1; t >= 1; t--) {
            tag = (int)bps[t * Tt + tag];
            tags[t - 1] = tag;
        }
    }
    __syncthreads();
    for (int t = tid; t < Ss; t += 32)
        outv[(size_t)b * Ss + t] = (float)tags[t];
}

// ---------------- launch ----------------
extern "C" void kernel_launch(void* const* d_in, const int* in_sizes, int n_in,
                              void* d_out, int out_size) {
    const int*   batch_char = (const int*)d_in[0];
    const int*   gaz_list   = (const int*)d_in[2];
    const int*   graphs[3]  = {(const int*)d_in[3], (const int*)d_in[4], (const int*)d_in[5]};
    const int*   mask       = (const int*)d_in[6];
    const float* char_table = (const float*)d_in[7];
    const float* gaz_table  = (const float*)d_in[8];
    const float* w_ih_f     = (const float*)d_in[9];
    const float* w_hh_f     = (const float*)d_in[10];
    const float* b_f        = (const float*)d_in[11];
    const float* w_ih_b     = (const float*)d_in[12];
    const float* w_hh_b     = (const float*)d_in[13];
    const float* b_b        = (const float*)d_in[14];
    const float* h2h_W      = (const float*)d_in[15];
    const float* h2h_b      = (const float*)d_in[16];
    const float* gat_Wh     = (const float*)d_in[17];
    const float* gat_ah     = (const float*)d_in[18];
    const float* gat_Wo     = (const float*)d_in[19];
    const float* gat_ao     = (const float*)d_in[20];
    const float* fuse_w     = (const float*)d_in[21];
    const float* trans      = (const float*)d_in[22];

    // xw = emb @ W_ih^T + b  (char-embedding gather fused into A-load)
    {
        dim3 grid(4, 96);
        gemm_kernel<<<grid, 256>>>(0, char_table, batch_char, w_ih_f, b_f,
                                   OFF_XWHH, BSROWS, 256, ECHAR, 1, 1, 1);
        gemm_kernel<<<grid, 256>>>(0, char_table, batch_char, w_ih_b, b_b,
                                   OFF_XWHH + BSROWS * 256, BSROWS, 256, ECHAR, 1, 1, 1);
    }
    embed_gaz_kernel<<<(Bb * Gg * Dd + 255) / 256, 256>>>(gaz_list, gaz_table);
    lstm_kernel<<<32, 256>>>(w_hh_f, w_hh_b);

    // lstm projection (lstm rows strided within gatin)
    gemm_kernel<<<dim3(1, 96), 256>>>(OFF_GATIN, nullptr, nullptr, h2h_W, h2h_b,
                                      OFF_LPROJ, BSROWS, Tt, Dd, 1, Ss, NTOK);

    for (int k = 0; k < 3; k++) {
        gemm_heads_kernel<<<dim3(4, 192), 256>>>(
            gat_Wh + (size_t)k * 4 * Dd * 64, gat_ah + (size_t)k * 4 * 128);
        attn1_kernel<<<dim3(NTOK, Bb), 256>>>(graphs[k],
                                              gat_Wo + (size_t)k * 256 * Tt,
                                              gat_ao + (size_t)k * 2 * Tt);
        attn2_kernel<<<dim3(Ss, Bb), 256>>>(graphs[k],
                                            OFF_GOUT + (unsigned)k * BSROWS * Tt);
    }

    fuse_kernel<<<(Bb * Ss * Tt + 255) / 256, 256>>>(fuse_w);
    viterbi_kernel<<<Bb, 32>>>(trans, mask, (float*)d_out);
}

// round 8
// speedup vs baseline: 1.4022x; 1.0642x over previous
#include <cuda_runtime.h>
#include <cstdint>
#include <math.h>

// Problem constants
#define Bb     16
#define Ss     384
#define Gg     384
#define NTOK   768
#define ECHAR  100
#define Dd     128
#define Tt     21
#define CSTART 19
#define CSTOP  20
#define BNROWS (Bb*NTOK)    // 12288
#define BSROWS (Bb*Ss)      // 6144

// scratch layout (floats) — ~16.0M floats = 64 MB
#define OFF_XW     0u                       // [2][6144][256]      3,145,728
#define OFF_GATIN  3145728u                 // [12288][128]        1,572,864
#define OFF_HH     4718592u                 // [3][4][12288][64]   9,437,184
#define OFF_F1     14155776u                // [3][4][12288]         147,456
#define OFF_F2     14303232u                //                       147,456
#define OFF_F1B    14450688u                // [3][12288]             36,864
#define OFF_F2B    14487552u                //                        36,864
#define OFF_H2     14524416u                // [3][12288][21]        774,144
#define OFF_LPROJ  15298560u                // [6144][21]            129,024
#define OFF_GOUT   15427584u                // [3][6144][21]         387,072
#define OFF_FEATS  15814656u                // [6144][21]            129,024
#define SCRATCH_TOTAL 15943680u

__device__ float g_scratch[SCRATCH_TOTAL];

// ---------------- gaz embedding gather ----------------
__global__ void embed_gaz_kernel(const int* __restrict__ gl,
                                 const float* __restrict__ tab) {
    int i = blockIdx.x * blockDim.x + threadIdx.x;
    if (i >= Bb * Gg * Dd) return;
    int r = i / Dd, f = i - r * Dd;
    int b = r / Gg, g = r - b * Gg;
    int idx = gl[r];
    if (idx < 0) idx = 0; if (idx >= 100000) idx = 99999;
    g_scratch[OFF_GATIN + ((size_t)b * NTOK + Ss + g) * Dd + f] =
        tab[(size_t)idx * Dd + f];
}

// ---------------- generic tiled fp32 GEMM (optional gathered-A) ----------------
// 64x64 tile, 4x4 contiguous per-thread micro-tile, float4 LDS, padded smem.
__global__ __launch_bounds__(256)
void gemm_kernel(unsigned aoff, const float* __restrict__ Aext,
                 const int* __restrict__ gidx,
                 const float* __restrict__ Bm, const float* __restrict__ bias,
                 unsigned coff, int M, int N, int K, int transB,
                 int arpb, int astr) {
    float* C = g_scratch + coff;
    __shared__ __align__(16) float As[16][68];
    __shared__ __align__(16) float Bs[16][68];
    int tid = threadIdx.x;
    int tx = tid & 15, ty = tid >> 4;
    int rowBase = blockIdx.y * 64;
    int colBase = blockIdx.x * 64;
    float acc[4][4] = {};
    for (int k0 = 0; k0 < K; k0 += 16) {
        for (int l = tid; l < 1024; l += 256) {
            int r = l >> 4, kk = l & 15;
            int gr = rowBase + r, gk = k0 + kk;
            float v = 0.f;
            if (gr < M && gk < K) {
                if (gidx) {
                    int ci = gidx[gr];
                    if (ci < 0) ci = 0; if (ci >= 8000) ci = 7999;
                    v = Aext[(size_t)ci * K + gk];
                } else {
                    int sr = (gr / arpb) * astr + (gr % arpb);
                    v = g_scratch[aoff + (size_t)sr * K + gk];
                }
            }
            As[kk][r] = v;
        }
        for (int l = tid; l < 1024; l += 256) {
            int kk = l >> 6, c = l & 63;
            int gk = k0 + kk, gc = colBase + c;
            float v = 0.f;
            if (gk < K && gc < N)
                v = transB ? Bm[(size_t)gc * K + gk] : Bm[(size_t)gk * N + gc];
            Bs[kk][c] = v;
        }
        __syncthreads();
        #pragma unroll
        for (int kk = 0; kk < 16; kk++) {
            float4 av = *(const float4*)&As[kk][ty * 4];
            float4 bv = *(const float4*)&Bs[kk][tx * 4];
            float a[4] = {av.x, av.y, av.z, av.w};
            float b[4] = {bv.x, bv.y, bv.z, bv.w};
            #pragma unroll
            for (int i = 0; i < 4; i++)
                #pragma unroll
                for (int j = 0; j < 4; j++)
                    acc[i][j] += a[i] * b[j];
        }
        __syncthreads();
    }
    #pragma unroll
    for (int i = 0; i < 4; i++) {
        int row = rowBase + ty * 4 + i;
        if (row >= M) continue;
        #pragma unroll
        for (int j = 0; j < 4; j++) {
            int col = colBase + tx * 4 + j;
            if (col >= N) continue;
            float v = acc[i][j];
            if (bias) v += bias[col];
            C[(size_t)row * N + col] = v;
        }
    }
}

// ---------------- head-projection GEMM with fused f1/f2 epilogue ----------------
// grid (4 heads, 192 row-tiles, 3 graphs). A = gatin [12288][128].
__global__ __launch_bounds__(256)
void gemm_heads_kernel(const float* __restrict__ WhAll, const float* __restrict__ ahAll) {
    int m = blockIdx.x, z = blockIdx.z;
    int hm = z * 4 + m;
    int rowBase = blockIdx.y * 64;
    const float* A = g_scratch + OFF_GATIN;
    const float* B = WhAll + (size_t)hm * (Dd * 64);
    float* C = g_scratch + OFF_HH + (size_t)hm * BNROWS * 64;
    __shared__ __align__(16) float As[16][68];
    __shared__ __align__(16) float Bs[16][68];
    int tid = threadIdx.x;
    int tx = tid & 15, ty = tid >> 4;
    float acc[4][4] = {};
    for (int k0 = 0; k0 < Dd; k0 += 16) {
        for (int l = tid; l < 1024; l += 256) {
            int r = l >> 4, kk = l & 15;
            As[kk][r] = A[(size_t)(rowBase + r) * Dd + k0 + kk];
        }
        for (int l = tid; l < 1024; l += 256) {
            int kk = l >> 6, c = l & 63;
            Bs[kk][c] = B[(size_t)(k0 + kk) * 64 + c];
        }
        __syncthreads();
        #pragma unroll
        for (int kk = 0; kk < 16; kk++) {
            float4 av = *(const float4*)&As[kk][ty * 4];
            float4 bv = *(const float4*)&Bs[kk][tx * 4];
            float a[4] = {av.x, av.y, av.z, av.w};
            float b[4] = {bv.x, bv.y, bv.z, bv.w};
            #pragma unroll
            for (int i = 0; i < 4; i++)
                #pragma unroll
                for (int j = 0; j < 4; j++)
                    acc[i][j] += a[i] * b[j];
        }
        __syncthreads();
    }
    const float* a1 = ahAll + (size_t)hm * 128;
    float av1[4], av2[4];
    #pragma unroll
    for (int j = 0; j < 4; j++) {
        av1[j] = a1[tx * 4 + j];
        av2[j] = a1[64 + tx * 4 + j];
    }
    #pragma unroll
    for (int i = 0; i < 4; i++) {
        int row = rowBase + ty * 4 + i;
        float p1 = 0.f, p2 = 0.f;
        float4 cv;
        cv.x = acc[i][0]; cv.y = acc[i][1]; cv.z = acc[i][2]; cv.w = acc[i][3];
        *(float4*)&C[(size_t)row * 64 + tx * 4] = cv;
        #pragma unroll
        for (int j = 0; j < 4; j++) {
            p1 += acc[i][j] * av1[j];
            p2 += acc[i][j] * av2[j];
        }
        #pragma unroll
        for (int off = 8; off > 0; off >>= 1) {
            p1 += __shfl_xor_sync(0xffffffffu, p1, off);
            p2 += __shfl_xor_sync(0xffffffffu, p2, off);
        }
        if (tx == 0) {
            g_scratch[OFF_F1 + (size_t)hm * BNROWS + row] = p1;
            g_scratch[OFF_F2 + (size_t)hm * BNROWS + row] = p2;
        }
    }
}

// ---------------- BiLSTM ----------------
// per-thread gate nonlinearity (all 256 threads), 64-thread combine.
__global__ __launch_bounds__(256)
void lstm_kernel(const float* __restrict__ whh_f, const float* __restrict__ whh_b) {
    int dir = blockIdx.x & 1, b = blockIdx.x >> 1;
    const float* whh = dir ? whh_b : whh_f;
    int g = threadIdx.x;
    float w[64];
    #pragma unroll
    for (int j = 0; j < 64; j++) w[j] = whh[g * 64 + j];
    __shared__ __align__(16) float hsh[64];
    __shared__ float gates[256];
    float creg = 0.f;
    if (g < 64) hsh[g] = 0.f;
    __syncthreads();
    const float* xwd = g_scratch + OFF_XW + (size_t)dir * BSROWS * 256
                       + (size_t)b * Ss * 256;
    float* gat_in = g_scratch + OFF_GATIN;
    int t = dir ? (Ss - 1) : 0;
    int dt = dir ? -1 : 1;
    bool iscell = (g >= 128 && g < 192);
    float xnext = xwd[(size_t)t * 256 + g];
    for (int step = 0; step < Ss; step++, t += dt) {
        float acc = xnext;
        if (step + 1 < Ss) xnext = xwd[(size_t)(t + dt) * 256 + g];  // prefetch
        const float4* h4 = (const float4*)hsh;
        float a0 = 0.f, a1 = 0.f, a2 = 0.f, a3 = 0.f;
        #pragma unroll
        for (int j4 = 0; j4 < 16; j4++) {
            float4 hv = h4[j4];
            a0 += hv.x * w[4 * j4];
            a1 += hv.y * w[4 * j4 + 1];
            a2 += hv.z * w[4 * j4 + 2];
            a3 += hv.w * w[4 * j4 + 3];
        }
        acc += (a0 + a1) + (a2 + a3);
        // apply own nonlinearity (parallel across all 4 SMSPs)
        gates[g] = iscell ? tanhf(acc) : 1.f / (1.f + expf(-acc));
        __syncthreads();
        if (g < 64) {
            creg = gates[64 + g] * creg + gates[g] * gates[128 + g];
            float h = gates[192 + g] * tanhf(creg);
            hsh[g] = h;
            gat_in[((size_t)b * NTOK + t) * Dd + dir * 64 + g] = h;
        }
        __syncthreads();
    }
}

// ---------------- fused GAT layer-1 attn + layer-2 projection ----------------
// grid (768, 16, 3)
__global__ __launch_bounds__(256)
void attn1_kernel(const int* __restrict__ adj0, const int* __restrict__ adj1,
                  const int* __restrict__ adj2,
                  const float* __restrict__ WoAll, const float* __restrict__ aoAll) {
    int z = blockIdx.z;
    const int* adj = (z == 0) ? adj0 : (z == 1) ? adj1 : adj2;
    const float* Wo = WoAll + (size_t)z * 256 * Tt;
    const float* ao = aoAll + (size_t)z * 2 * Tt;
    const float* f1 = g_scratch + OFF_F1 + (size_t)z * 4 * BNROWS;
    const float* f2 = g_scratch + OFF_F2 + (size_t)z * 4 * BNROWS;
    const float* hh = g_scratch + OFF_HH + (size_t)z * 4 * BNROWS * 64;
    int b = blockIdx.y, i = blockIdx.x;
    int tid = threadIdx.x;
    __shared__ int jl[768];
    __shared__ int wsum[8], wbase[8];
    __shared__ int nnzsh;
    __shared__ float psm[4 * 768];
    __shared__ float f2s[4 * 768];
    __shared__ float wred[4][8];
    __shared__ float gmax[4], gsum[4];
    __shared__ float hrow[256];
    __shared__ float h2s[21];

    for (int l = tid; l < 4 * 768; l += 256) {
        int m = l / 768;
        int jj = l - m * 768;
        f2s[l] = f2[(size_t)m * BNROWS + (size_t)b * 768 + jj];
    }

    const int* arow = adj + ((size_t)b * 768 + i) * 768;
    int local[3]; int c = 0;
    #pragma unroll
    for (int q = 0; q < 3; q++) {
        int j = tid * 3 + q;
        if (arow[j] > 0) local[c++] = j;
    }
    int lane = tid & 31, warp = tid >> 5;
    // warp-level inclusive scan of c
    int v = c;
    #pragma unroll
    for (int off = 1; off < 32; off <<= 1) {
        int n = __shfl_up_sync(0xffffffffu, v, off);
        if (lane >= off) v += n;
    }
    if (lane == 31) wsum[warp] = v;
    __syncthreads();
    if (tid == 0) {
        int base = 0;
        #pragma unroll
        for (int w = 0; w < 8; w++) { wbase[w] = base; base += wsum[w]; }
        nnzsh = base;
    }
    __syncthreads();
    int start = wbase[warp] + v - c;
    int nnz = nnzsh;
    for (int q = 0; q < c; q++) jl[start + q] = local[q];
    __syncthreads();

    float f1v[4];
    #pragma unroll
    for (int m = 0; m < 4; m++)
        f1v[m] = f1[(size_t)m * BNROWS + (size_t)b * 768 + i];
    float lmax[4] = {-3e38f, -3e38f, -3e38f, -3e38f};
    for (int idx = tid; idx < nnz; idx += 256) {
        int j = jl[idx];
        #pragma unroll
        for (int m = 0; m < 4; m++) {
            float e = f1v[m] + f2s[m * 768 + j];
            e = e > 0.f ? e : 0.2f * e;
            psm[m * 768 + idx] = e;
            lmax[m] = fmaxf(lmax[m], e);
        }
    }
    #pragma unroll
    for (int m = 0; m < 4; m++) {
        float vv = lmax[m];
        #pragma unroll
        for (int off = 16; off > 0; off >>= 1)
            vv = fmaxf(vv, __shfl_down_sync(0xffffffffu, vv, off));
        if (lane == 0) wred[m][warp] = vv;
    }
    __syncthreads();
    if (tid < 4) {
        float mm = -3e38f;
        for (int w = 0; w < 8; w++) mm = fmaxf(mm, wred[tid][w]);
        gmax[tid] = mm;
    }
    __syncthreads();

    float lsum[4] = {0.f, 0.f, 0.f, 0.f};
    for (int idx = tid; idx < nnz; idx += 256) {
        #pragma unroll
        for (int m = 0; m < 4; m++) {
            float vv = expf(psm[m * 768 + idx] - gmax[m]);
            psm[m * 768 + idx] = vv;
            lsum[m] += vv;
        }
    }
    #pragma unroll
    for (int m = 0; m < 4; m++) {
        float vv = lsum[m];
        #pragma unroll
        for (int off = 16; off > 0; off >>= 1)
            vv += __shfl_down_sync(0xffffffffu, vv, off);
        if (lane == 0) wred[m][warp] = vv;
    }
    __syncthreads();
    if (tid < 4) {
        float ss = 0.f;
        for (int w = 0; w < 8; w++) ss += wred[tid][w];
        gsum[tid] = ss;
    }
    __syncthreads();

    // per-head aggregate + ELU -> hrow[256] (head-major layout)
    {
        int m = tid >> 6, f = tid & 63;
        const float* hp = hh + ((size_t)m * BNROWS + (size_t)b * 768) * 64 + f;
        float acc = 0.f;
        #pragma unroll 4
        for (int idx = 0; idx < nnz; idx++)
            acc += psm[m * 768 + idx] * hp[(size_t)jl[idx] * 64];
        float denom = gsum[m];
        acc = (denom > 0.f) ? acc / denom : 0.f;
        acc = acc > 0.f ? acc : expm1f(acc);
        hrow[tid] = acc;
    }
    __syncthreads();

    // layer-2 projection h2 = hrow @ Wo
    if (tid < 21) {
        float acc = 0.f;
        #pragma unroll 8
        for (int cix = 0; cix < 256; cix++)
            acc += hrow[cix] * Wo[cix * 21 + tid];
        g_scratch[OFF_H2 + ((size_t)z * BNROWS + (size_t)b * 768 + i) * 21 + tid] = acc;
        h2s[tid] = acc;
    }
    __syncthreads();
    if (tid < 2) {
        const float* av = ao + tid * 21;
        float s = 0.f;
        for (int t = 0; t < 21; t++) s += h2s[t] * av[t];
        g_scratch[(tid == 0 ? OFF_F1B : OFF_F2B) + (size_t)z * BNROWS
                  + (size_t)b * 768 + i] = s;
    }
}

// ---------------- GAT layer-2 sparse attention (1 head, F=21) ----------------
// grid (384, 16, 3)
__global__ __launch_bounds__(256)
void attn2_kernel(const int* __restrict__ adj0, const int* __restrict__ adj1,
                  const int* __restrict__ adj2) {
    int z = blockIdx.z;
    const int* adj = (z == 0) ? adj0 : (z == 1) ? adj1 : adj2;
    const float* f1 = g_scratch + OFF_F1B + (size_t)z * BNROWS;
    const float* f2 = g_scratch + OFF_F2B + (size_t)z * BNROWS;
    const float* h2 = g_scratch + OFF_H2 + (size_t)z * BNROWS * 21;
    unsigned outoff = OFF_GOUT + (unsigned)z * BSROWS * Tt;
    int b = blockIdx.y, i = blockIdx.x;  // i < Ss
    int tid = threadIdx.x;
    __shared__ int jl[768];
    __shared__ int wsum[8], wbase[8];
    __shared__ int nnzsh;
    __shared__ float psm[768];
    __shared__ float f2s[768];
    __shared__ float wred[8];
    __shared__ float gmax1, gsum1;

    for (int l = tid; l < 768; l += 256)
        f2s[l] = f2[(size_t)b * 768 + l];

    const int* arow = adj + ((size_t)b * 768 + i) * 768;
    int local[3]; int c = 0;
    #pragma unroll
    for (int q = 0; q < 3; q++) {
        int j = tid * 3 + q;
        if (arow[j] > 0) local[c++] = j;
    }
    int lane = tid & 31, warp = tid >> 5;
    int v = c;
    #pragma unroll
    for (int off = 1; off < 32; off <<= 1) {
        int n = __shfl_up_sync(0xffffffffu, v, off);
        if (lane >= off) v += n;
    }
    if (lane == 31) wsum[warp] = v;
    __syncthreads();
    if (tid == 0) {
        int base = 0;
        #pragma unroll
        for (int w = 0; w < 8; w++) { wbase[w] = base; base += wsum[w]; }
        nnzsh = base;
    }
    __syncthreads();
    int start = wbase[warp] + v - c;
    int nnz = nnzsh;
    for (int q = 0; q < c; q++) jl[start + q] = local[q];
    __syncthreads();

    float f1v = f1[(size_t)b * 768 + i];
    float lmax = -3e38f;
    for (int idx = tid; idx < nnz; idx += 256) {
        float e = f1v + f2s[jl[idx]];
        e = e > 0.f ? e : 0.2f * e;
        psm[idx] = e;
        lmax = fmaxf(lmax, e);
    }
    #pragma unroll
    for (int off = 16; off > 0; off >>= 1)
        lmax = fmaxf(lmax, __shfl_down_sync(0xffffffffu, lmax, off));
    if (lane == 0) wred[warp] = lmax;
    __syncthreads();
    if (tid == 0) {
        float mm = -3e38f;
        for (int w = 0; w < 8; w++) mm = fmaxf(mm, wred[w]);
        gmax1 = mm;
    }
    __syncthreads();

    float lsum = 0.f;
    for (int idx = tid; idx < nnz; idx += 256) {
        float vv = expf(psm[idx] - gmax1);
        psm[idx] = vv;
        lsum += vv;
    }
    #pragma unroll
    for (int off = 16; off > 0; off >>= 1)
        lsum += __shfl_down_sync(0xffffffffu, lsum, off);
    if (lane == 0) wred[warp] = lsum;
    __syncthreads();
    if (tid == 0) {
        float ss = 0.f;
        for (int w = 0; w < 8; w++) ss += wred[w];
        gsum1 = ss;
    }
    __syncthreads();

    if (tid < 21) {
        const float* hp = h2 + (size_t)b * 768 * 21 + tid;
        float acc = 0.f;
        #pragma unroll 4
        for (int idx = 0; idx < nnz; idx++)
            acc += psm[idx] * hp[(size_t)jl[idx] * 21];
        float denom = gsum1;
        acc = (denom > 0.f) ? acc / denom : 0.f;
        acc = acc > 0.f ? acc : expm1f(acc);
        g_scratch[outoff + ((size_t)b * Ss + i) * 21 + tid] = acc;
    }
}

// ---------------- fuse ----------------
__global__ void fuse_kernel(const float* __restrict__ fw) {
    int i = blockIdx.x * blockDim.x + threadIdx.x;
    if (i >= Bb * Ss * Tt) return;
    const float* lproj = g_scratch + OFF_LPROJ;
    const float* g0 = g_scratch + OFF_GOUT;
    const float* g1 = g0 + BSROWS * Tt;
    const float* g2 = g1 + BSROWS * Tt;
    g_scratch[OFF_FEATS + i] =
        fw[0] * lproj[i] + fw[1] * g0[i] + fw[2] * g1[i] + fw[3] * g2[i];
}

// ---------------- Viterbi (float32 output) ----------------
__global__ __launch_bounds__(32)
void viterbi_kernel(const float* __restrict__ trans,
                    const int* __restrict__ mask, float* __restrict__ outv) {
    const float* feats = g_scratch + OFF_FEATS;
    int b = blockIdx.x;
    int tid = threadIdx.x;
    __shared__ float part[21], np[21];
    __shared__ float trsh[441];
    __shared__ short bps[Ss * Tt];
    __shared__ int tags[Ss];
    for (int l = tid; l < 441; l += 32) trsh[l] = trans[l];
    __syncthreads();
    if (tid < 21)
        part[tid] = feats[((size_t)b * Ss) * Tt + tid] + trsh[CSTART * 21 + tid];
    __syncthreads();
    for (int t = 1; t < Ss; t++) {
        if (tid < 21) {
            float ft = feats[((size_t)b * Ss + t) * Tt + tid];
            float best = -3e38f; int bi = 0;
            #pragma unroll
            for (int p = 0; p < 21; p++) {
                float v = part[p] + trsh[p * 21 + tid] + ft;
                if (v > best) { best = v; bi = p; }
            }
            int m = mask[b * Ss + t];
            np[tid] = (m > 0) ? best : part[tid];
            bps[t * Tt + tid] = (short)((m > 0) ? bi : tid);
        }
        __syncthreads();
        if (tid < 21) part[tid] = np[tid];
        __syncthreads();
    }
    if (tid == 0) {
        float best = -3e38f; int bt = 0;
        for (int p = 0; p < 21; p++) {
            float v = part[p] + trsh[p * 21 + CSTOP];
            if (v > best) { best = v; bt = p; }
        }
        tags[Ss - 1] = bt;
        int tag = bt;
        for (int t = Ss - 1; t >= 1; t--) {
            tag = (int)bps[t * Tt + tag];
            tags[t - 1] = tag;
        }
    }
    __syncthreads();
    for (int t = tid; t < Ss; t += 32)
        outv[(size_t)b * Ss + t] = (float)tags[t];
}

// ---------------- launch ----------------
extern "C" void kernel_launch(void* const* d_in, const int* in_sizes, int n_in,
                              void* d_out, int out_size) {
    const int*   batch_char = (const int*)d_in[0];
    const int*   gaz_list   = (const int*)d_in[2];
    const int*   adj0       = (const int*)d_in[3];
    const int*   adj1       = (const int*)d_in[4];
    const int*   adj2       = (const int*)d_in[5];
    const int*   mask       = (const int*)d_in[6];
    const float* char_table = (const float*)d_in[7];
    const float* gaz_table  = (const float*)d_in[8];
    const float* w_ih_f     = (const float*)d_in[9];
    const float* w_hh_f     = (const float*)d_in[10];
    const float* b_f        = (const float*)d_in[11];
    const float* w_ih_b     = (const float*)d_in[12];
    const float* w_hh_b     = (const float*)d_in[13];
    const float* b_b        = (const float*)d_in[14];
    const float* h2h_W      = (const float*)d_in[15];
    const float* h2h_b      = (const float*)d_in[16];
    const float* gat_Wh     = (const float*)d_in[17];
    const float* gat_ah     = (const float*)d_in[18];
    const float* gat_Wo     = (const float*)d_in[19];
    const float* gat_ao     = (const float*)d_in[20];
    const float* fuse_w     = (const float*)d_in[21];
    const float* trans      = (const float*)d_in[22];

    // xw = emb @ W_ih^T + b  (char-embedding gather fused into A-load)
    {
        dim3 grid(4, 96);
        gemm_kernel<<<grid, 256>>>(0, char_table, batch_char, w_ih_f, b_f,
                                   OFF_XW, BSROWS, 256, ECHAR, 1, 1, 1);
        gemm_kernel<<<grid, 256>>>(0, char_table, batch_char, w_ih_b, b_b,
                                   OFF_XW + BSROWS * 256, BSROWS, 256, ECHAR, 1, 1, 1);
    }
    embed_gaz_kernel<<<(Bb * Gg * Dd + 255) / 256, 256>>>(gaz_list, gaz_table);
    lstm_kernel<<<32, 256>>>(w_hh_f, w_hh_b);

    // lstm projection (lstm rows strided within gatin)
    gemm_kernel<<<dim3(1, 96), 256>>>(OFF_GATIN, nullptr, nullptr, h2h_W, h2h_b,
                                      OFF_LPROJ, BSROWS, Tt, Dd, 1, Ss, NTOK);

    // all three graphs in one launch each
    gemm_heads_kernel<<<dim3(4, 192, 3), 256>>>(gat_Wh, gat_ah);
    attn1_kernel<<<dim3(NTOK, Bb, 3), 256>>>(adj0, adj1, adj2, gat_Wo, gat_ao);
    attn2_kernel<<<dim3(Ss, Bb, 3), 256>>>(adj0, adj1, adj2);

    fuse_kernel<<<(Bb * Ss * Tt + 255) / 256, 256>>>(fuse_w);
    viterbi_kernel<<<Bb, 32>>>(trans, mask, (float*)d_out);
}

// round 9
// speedup vs baseline: 1.4165x; 1.0102x over previous
#include <cuda_runtime.h>
#include <cstdint>
#include <math.h>

// Problem constants
#define Bb     16
#define Ss     384
#define Gg     384
#define NTOK   768
#define ECHAR  100
#define Dd     128
#define Tt     21
#define CSTART 19
#define CSTOP  20
#define BNROWS (Bb*NTOK)    // 12288
#define BSROWS (Bb*Ss)      // 6144

// scratch layout (floats)
#define OFF_XW     0u                       // [2][6144][256]      3,145,728
#define OFF_GATIN  3145728u                 // [12288][128]        1,572,864
#define OFF_HH     4718592u                 // [3][4][12288][64]   9,437,184
#define OFF_F1     14155776u                // [3][4][12288]         147,456
#define OFF_F2     14303232u                //                       147,456
#define OFF_F1B    14450688u                // [3][12288]             36,864
#define OFF_F2B    14487552u                //                        36,864
#define OFF_H2     14524416u                // [3][12288][21]        774,144
#define OFF_LPROJ  15298560u                // [6144][21]            129,024
#define OFF_GOUT   15427584u                // [3][6144][21]         387,072
#define OFF_FEATS  15814656u                // [6144][21]            129,024
#define OFF_HCAT   15943680u                // [3][12288][256]     9,437,184
#define SCRATCH_TOTAL 25380864u

__device__ float g_scratch[SCRATCH_TOTAL];

// dynamic smem for attn1_agg: h 768*64 f32 + f2s 768 f32 + psj 8*256 float2
#define SMEM_ATTN1 ((49152 + 768) * 4 + 8 * 256 * 8)   // 216,064 B

// ---------------- gaz embedding gather ----------------
__global__ void embed_gaz_kernel(const int* __restrict__ gl,
                                 const float* __restrict__ tab) {
    int i = blockIdx.x * blockDim.x + threadIdx.x;
    if (i >= Bb * Gg * Dd) return;
    int r = i / Dd, f = i - r * Dd;
    int b = r / Gg, g = r - b * Gg;
    int idx = gl[r];
    if (idx < 0) idx = 0; if (idx >= 100000) idx = 99999;
    g_scratch[OFF_GATIN + ((size_t)b * NTOK + Ss + g) * Dd + f] =
        tab[(size_t)idx * Dd + f];
}

// ---------------- generic tiled fp32 GEMM (optional gathered-A) ----------------
__global__ __launch_bounds__(256)
void gemm_kernel(unsigned aoff, const float* __restrict__ Aext,
                 const int* __restrict__ gidx,
                 const float* __restrict__ Bm, const float* __restrict__ bias,
                 unsigned coff, int M, int N, int K, int transB,
                 int arpb, int astr) {
    float* C = g_scratch + coff;
    __shared__ __align__(16) float As[16][68];
    __shared__ __align__(16) float Bs[16][68];
    int tid = threadIdx.x;
    int tx = tid & 15, ty = tid >> 4;
    int rowBase = blockIdx.y * 64;
    int colBase = blockIdx.x * 64;
    float acc[4][4] = {};
    for (int k0 = 0; k0 < K; k0 += 16) {
        for (int l = tid; l < 1024; l += 256) {
            int r = l >> 4, kk = l & 15;
            int gr = rowBase + r, gk = k0 + kk;
            float v = 0.f;
            if (gr < M && gk < K) {
                if (gidx) {
                    int ci = gidx[gr];
                    if (ci < 0) ci = 0; if (ci >= 8000) ci = 7999;
                    v = Aext[(size_t)ci * K + gk];
                } else {
                    int sr = (gr / arpb) * astr + (gr % arpb);
                    v = g_scratch[aoff + (size_t)sr * K + gk];
                }
            }
            As[kk][r] = v;
        }
        for (int l = tid; l < 1024; l += 256) {
            int kk = l >> 6, c = l & 63;
            int gk = k0 + kk, gc = colBase + c;
            float v = 0.f;
            if (gk < K && gc < N)
                v = transB ? Bm[(size_t)gc * K + gk] : Bm[(size_t)gk * N + gc];
            Bs[kk][c] = v;
        }
        __syncthreads();
        #pragma unroll
        for (int kk = 0; kk < 16; kk++) {
            float4 av = *(const float4*)&As[kk][ty * 4];
            float4 bv = *(const float4*)&Bs[kk][tx * 4];
            float a[4] = {av.x, av.y, av.z, av.w};
            float b[4] = {bv.x, bv.y, bv.z, bv.w};
            #pragma unroll
            for (int i = 0; i < 4; i++)
                #pragma unroll
                for (int j = 0; j < 4; j++)
                    acc[i][j] += a[i] * b[j];
        }
        __syncthreads();
    }
    #pragma unroll
    for (int i = 0; i < 4; i++) {
        int row = rowBase + ty * 4 + i;
        if (row >= M) continue;
        #pragma unroll
        for (int j = 0; j < 4; j++) {
            int col = colBase + tx * 4 + j;
            if (col >= N) continue;
            float v = acc[i][j];
            if (bias) v += bias[col];
            C[(size_t)row * N + col] = v;
        }
    }
}

// ---------------- head-projection GEMM with fused f1/f2 epilogue ----------------
__global__ __launch_bounds__(256)
void gemm_heads_kernel(const float* __restrict__ WhAll, const float* __restrict__ ahAll) {
    int m = blockIdx.x, z = blockIdx.z;
    int hm = z * 4 + m;
    int rowBase = blockIdx.y * 64;
    const float* A = g_scratch + OFF_GATIN;
    const float* B = WhAll + (size_t)hm * (Dd * 64);
    float* C = g_scratch + OFF_HH + (size_t)hm * BNROWS * 64;
    __shared__ __align__(16) float As[16][68];
    __shared__ __align__(16) float Bs[16][68];
    int tid = threadIdx.x;
    int tx = tid & 15, ty = tid >> 4;
    float acc[4][4] = {};
    for (int k0 = 0; k0 < Dd; k0 += 16) {
        for (int l = tid; l < 1024; l += 256) {
            int r = l >> 4, kk = l & 15;
            As[kk][r] = A[(size_t)(rowBase + r) * Dd + k0 + kk];
        }
        for (int l = tid; l < 1024; l += 256) {
            int kk = l >> 6, c = l & 63;
            Bs[kk][c] = B[(size_t)(k0 + kk) * 64 + c];
        }
        __syncthreads();
        #pragma unroll
        for (int kk = 0; kk < 16; kk++) {
            float4 av = *(const float4*)&As[kk][ty * 4];
            float4 bv = *(const float4*)&Bs[kk][tx * 4];
            float a[4] = {av.x, av.y, av.z, av.w};
            float b[4] = {bv.x, bv.y, bv.z, bv.w};
            #pragma unroll
            for (int i = 0; i < 4; i++)
                #pragma unroll
                for (int j = 0; j < 4; j++)
                    acc[i][j] += a[i] * b[j];
        }
        __syncthreads();
    }
    const float* a1 = ahAll + (size_t)hm * 128;
    float av1[4], av2[4];
    #pragma unroll
    for (int j = 0; j < 4; j++) {
        av1[j] = a1[tx * 4 + j];
        av2[j] = a1[64 + tx * 4 + j];
    }
    #pragma unroll
    for (int i = 0; i < 4; i++) {
        int row = rowBase + ty * 4 + i;
        float p1 = 0.f, p2 = 0.f;
        float4 cv;
        cv.x = acc[i][0]; cv.y = acc[i][1]; cv.z = acc[i][2]; cv.w = acc[i][3];
        *(float4*)&C[(size_t)row * 64 + tx * 4] = cv;
        #pragma unroll
        for (int j = 0; j < 4; j++) {
            p1 += acc[i][j] * av1[j];
            p2 += acc[i][j] * av2[j];
        }
        #pragma unroll
        for (int off = 8; off > 0; off >>= 1) {
            p1 += __shfl_xor_sync(0xffffffffu, p1, off);
            p2 += __shfl_xor_sync(0xffffffffu, p2, off);
        }
        if (tx == 0) {
            g_scratch[OFF_F1 + (size_t)hm * BNROWS + row] = p1;
            g_scratch[OFF_F2 + (size_t)hm * BNROWS + row] = p2;
        }
    }
}

// ---------------- BiLSTM ----------------
__global__ __launch_bounds__(256)
void lstm_kernel(const float* __restrict__ whh_f, const float* __restrict__ whh_b) {
    int dir = blockIdx.x & 1, b = blockIdx.x >> 1;
    const float* whh = dir ? whh_b : whh_f;
    int g = threadIdx.x;
    float w[64];
    #pragma unroll
    for (int j = 0; j < 64; j++) w[j] = whh[g * 64 + j];
    __shared__ __align__(16) float hsh[64];
    __shared__ float gates[256];
    float creg = 0.f;
    if (g < 64) hsh[g] = 0.f;
    __syncthreads();
    const float* xwd = g_scratch + OFF_XW + (size_t)dir * BSROWS * 256
                       + (size_t)b * Ss * 256;
    float* gat_in = g_scratch + OFF_GATIN;
    int t = dir ? (Ss - 1) : 0;
    int dt = dir ? -1 : 1;
    bool iscell = (g >= 128 && g < 192);
    float xnext = xwd[(size_t)t * 256 + g];
    for (int step = 0; step < Ss; step++, t += dt) {
        float acc = xnext;
        if (step + 1 < Ss) xnext = xwd[(size_t)(t + dt) * 256 + g];
        const float4* h4 = (const float4*)hsh;
        float a0 = 0.f, a1 = 0.f, a2 = 0.f, a3 = 0.f;
        #pragma unroll
        for (int j4 = 0; j4 < 16; j4++) {
            float4 hv = h4[j4];
            a0 += hv.x * w[4 * j4];
            a1 += hv.y * w[4 * j4 + 1];
            a2 += hv.z * w[4 * j4 + 2];
            a3 += hv.w * w[4 * j4 + 3];
        }
        acc += (a0 + a1) + (a2 + a3);
        gates[g] = iscell ? tanhf(acc) : 1.f / (1.f + expf(-acc));
        __syncthreads();
        if (g < 64) {
            creg = gates[64 + g] * creg + gates[g] * gates[128 + g];
            float h = gates[192 + g] * tanhf(creg);
            hsh[g] = h;
            gat_in[((size_t)b * NTOK + t) * Dd + dir * 64 + g] = h;
        }
        __syncthreads();
    }
}

// ---------------- GAT layer-1 aggregation: h panel in smem, warp-per-row ----------------
// grid (2 chunks, 64 = m*16+b, 3 z); block 256 (8 warps); dyn smem SMEM_ATTN1.
__global__ __launch_bounds__(256)
void attn1_agg_kernel(const int* __restrict__ adj0, const int* __restrict__ adj1,
                      const int* __restrict__ adj2) {
    extern __shared__ __align__(16) float smem[];
    float* hsm = smem;                           // 49152 floats
    float* f2s = smem + 49152;                   // 768
    float2* psj = (float2*)(smem + 49152 + 768); // 8 warps x 256
    int z = blockIdx.z;
    int m = blockIdx.y >> 4, b = blockIdx.y & 15;
    int chunk = blockIdx.x;
    const int* adj = (z == 0) ? adj0 : (z == 1) ? adj1 : adj2;
    int hm = z * 4 + m;
    int tid = threadIdx.x, lane = tid & 31, w = tid >> 5;

    // load h[m,b] panel (768x64) into smem
    const float4* hsrc = (const float4*)(g_scratch + OFF_HH
                         + ((size_t)hm * BNROWS + (size_t)b * 768) * 64);
    float4* hdst = (float4*)hsm;
    for (int l = tid; l < 12288; l += 256) hdst[l] = hsrc[l];
    const float* f2g = g_scratch + OFF_F2 + (size_t)hm * BNROWS + (size_t)b * 768;
    for (int l = tid; l < 768; l += 256) f2s[l] = f2g[l];
    __syncthreads();

    float2* mypsj = psj + w * 256;
    const float* f1g = g_scratch + OFF_F1 + (size_t)hm * BNROWS + (size_t)b * 768;
    float* hcat = g_scratch + OFF_HCAT + (size_t)z * BNROWS * 256;
    const float2* h2p = (const float2*)hsm;

    for (int i = chunk * 384 + w; i < chunk * 384 + 384; i += 8) {
        const int4* arow = (const int4*)(adj + ((size_t)b * 768 + i) * 768 + lane * 24);
        int4 a[6];
        #pragma unroll
        for (int q = 0; q < 6; q++) a[q] = arow[q];
        int c = 0;
        #pragma unroll
        for (int q = 0; q < 6; q++)
            c += (a[q].x > 0) + (a[q].y > 0) + (a[q].z > 0) + (a[q].w > 0);
        // warp inclusive scan -> start/nnz
        int pos = c;
        #pragma unroll
        for (int off = 1; off < 32; off <<= 1) {
            int n = __shfl_up_sync(0xffffffffu, pos, off);
            if (lane >= off) pos += n;
        }
        int nnz = __shfl_sync(0xffffffffu, pos, 31);
        pos -= c;  // exclusive start
        float f1i = f1g[i];
        int jbase = lane * 24;
        #pragma unroll
        for (int q = 0; q < 6; q++) {
            int vals[4] = {a[q].x, a[q].y, a[q].z, a[q].w};
            #pragma unroll
            for (int r = 0; r < 4; r++) {
                if (vals[r] > 0) {
                    int j = jbase + q * 4 + r;
                    float e = f1i + f2s[j];
                    e = e > 0.f ? e : 0.2f * e;
                    mypsj[pos] = make_float2(e, __int_as_float(j));
                    pos++;
                }
            }
        }
        __syncwarp();
        float mx = -3e38f;
        for (int idx = lane; idx < nnz; idx += 32) mx = fmaxf(mx, mypsj[idx].x);
        #pragma unroll
        for (int off = 16; off > 0; off >>= 1)
            mx = fmaxf(mx, __shfl_xor_sync(0xffffffffu, mx, off));
        float sm = 0.f;
        for (int idx = lane; idx < nnz; idx += 32) {
            float p = expf(mypsj[idx].x - mx);
            mypsj[idx].x = p;
            sm += p;
        }
        #pragma unroll
        for (int off = 16; off > 0; off >>= 1)
            sm += __shfl_xor_sync(0xffffffffu, sm, off);
        __syncwarp();
        float2 acc = make_float2(0.f, 0.f);
        for (int idx = 0; idx < nnz; idx++) {
            float2 pj = mypsj[idx];
            int j = __float_as_int(pj.y);
            float2 hv = h2p[j * 32 + lane];
            acc.x += pj.x * hv.x;
            acc.y += pj.x * hv.y;
        }
        acc.x /= sm;
        acc.y /= sm;
        acc.x = acc.x > 0.f ? acc.x : expm1f(acc.x);
        acc.y = acc.y > 0.f ? acc.y : expm1f(acc.y);
        ((float2*)(hcat + ((size_t)b * 768 + i) * 256 + m * 64))[lane] = acc;
        __syncwarp();
    }
}

// ---------------- f1b/f2b: per-row dot with ao (warp per row) ----------------
__global__ __launch_bounds__(256)
void f1f2b_kernel(const float* __restrict__ aoAll) {
    int row = blockIdx.x * 8 + (threadIdx.x >> 5);
    int lane = threadIdx.x & 31;
    if (row >= 3 * BNROWS) return;
    int z = row / BNROWS;
    const float* ao = aoAll + (size_t)z * 42;
    const float* h2r = g_scratch + OFF_H2 + (size_t)row * 21;
    float v = (lane < 21) ? h2r[lane] : 0.f;
    float s1 = (lane < 21) ? v * ao[lane] : 0.f;
    float s2 = (lane < 21) ? v * ao[21 + lane] : 0.f;
    #pragma unroll
    for (int off = 16; off > 0; off >>= 1) {
        s1 += __shfl_xor_sync(0xffffffffu, s1, off);
        s2 += __shfl_xor_sync(0xffffffffu, s2, off);
    }
    if (lane == 0) {
        g_scratch[OFF_F1B + row] = s1;
        g_scratch[OFF_F2B + row] = s2;
    }
}

// ---------------- GAT layer-2 sparse attention (1 head, F=21) ----------------
__global__ __launch_bounds__(256)
void attn2_kernel(const int* __restrict__ adj0, const int* __restrict__ adj1,
                  const int* __restrict__ adj2) {
    int z = blockIdx.z;
    const int* adj = (z == 0) ? adj0 : (z == 1) ? adj1 : adj2;
    const float* f1 = g_scratch + OFF_F1B + (size_t)z * BNROWS;
    const float* f2 = g_scratch + OFF_F2B + (size_t)z * BNROWS;
    const float* h2 = g_scratch + OFF_H2 + (size_t)z * BNROWS * 21;
    unsigned outoff = OFF_GOUT + (unsigned)z * BSROWS * Tt;
    int b = blockIdx.y, i = blockIdx.x;  // i < Ss
    int tid = threadIdx.x;
    __shared__ int jl[768];
    __shared__ int wsum[8], wbase[8];
    __shared__ int nnzsh;
    __shared__ float psm[768];
    __shared__ float f2s[768];
    __shared__ float wred[8];
    __shared__ float gmax1, gsum1;

    for (int l = tid; l < 768; l += 256)
        f2s[l] = f2[(size_t)b * 768 + l];

    const int* arow = adj + ((size_t)b * 768 + i) * 768;
    int local[3]; int c = 0;
    #pragma unroll
    for (int q = 0; q < 3; q++) {
        int j = tid * 3 + q;
        if (arow[j] > 0) local[c++] = j;
    }
    int lane = tid & 31, warp = tid >> 5;
    int v = c;
    #pragma unroll
    for (int off = 1; off < 32; off <<= 1) {
        int n = __shfl_up_sync(0xffffffffu, v, off);
        if (lane >= off) v += n;
    }
    if (lane == 31) wsum[warp] = v;
    __syncthreads();
    if (tid == 0) {
        int base = 0;
        #pragma unroll
        for (int w = 0; w < 8; w++) { wbase[w] = base; base += wsum[w]; }
        nnzsh = base;
    }
    __syncthreads();
    int start = wbase[warp] + v - c;
    int nnz = nnzsh;
    for (int q = 0; q < c; q++) jl[start + q] = local[q];
    __syncthreads();

    float f1v = f1[(size_t)b * 768 + i];
    float lmax = -3e38f;
    for (int idx = tid; idx < nnz; idx += 256) {
        float e = f1v + f2s[jl[idx]];
        e = e > 0.f ? e : 0.2f * e;
        psm[idx] = e;
        lmax = fmaxf(lmax, e);
    }
    #pragma unroll
    for (int off = 16; off > 0; off >>= 1)
        lmax = fmaxf(lmax, __shfl_down_sync(0xffffffffu, lmax, off));
    if (lane == 0) wred[warp] = lmax;
    __syncthreads();
    if (tid == 0) {
        float mm = -3e38f;
        for (int w = 0; w < 8; w++) mm = fmaxf(mm, wred[w]);
        gmax1 = mm;
    }
    __syncthreads();

    float lsum = 0.f;
    for (int idx = tid; idx < nnz; idx += 256) {
        float vv = expf(psm[idx] - gmax1);
        psm[idx] = vv;
        lsum += vv;
    }
    #pragma unroll
    for (int off = 16; off > 0; off >>= 1)
        lsum += __shfl_down_sync(0xffffffffu, lsum, off);
    if (lane == 0) wred[warp] = lsum;
    __syncthreads();
    if (tid == 0) {
        float ss = 0.f;
        for (int w = 0; w < 8; w++) ss += wred[w];
        gsum1 = ss;
    }
    __syncthreads();

    if (tid < 21) {
        const float* hp = h2 + (size_t)b * 768 * 21 + tid;
        float acc = 0.f;
        #pragma unroll 4
        for (int idx = 0; idx < nnz; idx++)
            acc += psm[idx] * hp[(size_t)jl[idx] * 21];
        float denom = gsum1;
        acc = (denom > 0.f) ? acc / denom : 0.f;
        acc = acc > 0.f ? acc : expm1f(acc);
        g_scratch[outoff + ((size_t)b * Ss + i) * 21 + tid] = acc;
    }
}

// ---------------- fuse ----------------
__global__ void fuse_kernel(const float* __restrict__ fw) {
    int i = blockIdx.x * blockDim.x + threadIdx.x;
    if (i >= Bb * Ss * Tt) return;
    const float* lproj = g_scratch + OFF_LPROJ;
    const float* g0 = g_scratch + OFF_GOUT;
    const float* g1 = g0 + BSROWS * Tt;
    const float* g2 = g1 + BSROWS * Tt;
    g_scratch[OFF_FEATS + i] =
        fw[0] * lproj[i] + fw[1] * g0[i] + fw[2] * g1[i] + fw[3] * g2[i];
}

// ---------------- Viterbi (float32 output) ----------------
__global__ __launch_bounds__(32)
void viterbi_kernel(const float* __restrict__ trans,
                    const int* __restrict__ mask, float* __restrict__ outv) {
    const float* feats = g_scratch + OFF_FEATS;
    int b = blockIdx.x;
    int tid = threadIdx.x;
    __shared__ float part[21], np[21];
    __shared__ float trsh[441];
    __shared__ short bps[Ss * Tt];
    __shared__ int tags[Ss];
    for (int l = tid; l < 441; l += 32) trsh[l] = trans[l];
    __syncthreads();
    if (tid < 21)
        part[tid] = feats[((size_t)b * Ss) * Tt + tid] + trsh[CSTART * 21 + tid];
    __syncthreads();
    for (int t = 1; t < Ss; t++) {
        if (tid < 21) {
            float ft = feats[((size_t)b * Ss + t) * Tt + tid];
            float best = -3e38f; int bi = 0;
            #pragma unroll
            for (int p = 0; p < 21; p++) {
                float v = part[p] + trsh[p * 21 + tid] + ft;
                if (v > best) { best = v; bi = p; }
            }
            int m = mask[b * Ss + t];
            np[tid] = (m > 0) ? best : part[tid];
            bps[t * Tt + tid] = (short)((m > 0) ? bi : tid);
        }
        __syncthreads();
        if (tid < 21) part[tid] = np[tid];
        __syncthreads();
    }
    if (tid == 0) {
        float best = -3e38f; int bt = 0;
        for (int p = 0; p < 21; p++) {
            float v = part[p] + trsh[p * 21 + CSTOP];
            if (v > best) { best = v; bt = p; }
        }
        tags[Ss - 1] = bt;
        int tag = bt;
        for (int t = Ss - 1; t >= 1; t--) {
            tag = (int)bps[t * Tt + tag];
            tags[t - 1] = tag;
        }
    }
    __syncthreads();
    for (int t = tid; t < Ss; t += 32)
        outv[(size_t)b * Ss + t] = (float)tags[t];
}

// ---------------- launch ----------------
extern "C" void kernel_launch(void* const* d_in, const int* in_sizes, int n_in,
                              void* d_out, int out_size) {
    const int*   batch_char = (const int*)d_in[0];
    const int*   gaz_list   = (const int*)d_in[2];
    const int*   adj0       = (const int*)d_in[3];
    const int*   adj1       = (const int*)d_in[4];
    const int*   adj2       = (const int*)d_in[5];
    const int*   mask       = (const int*)d_in[6];
    const float* char_table = (const float*)d_in[7];
    const float* gaz_table  = (const float*)d_in[8];
    const float* w_ih_f     = (const float*)d_in[9];
    const float* w_hh_f     = (const float*)d_in[10];
    const float* b_f        = (const float*)d_in[11];
    const float* w_ih_b     = (const float*)d_in[12];
    const float* w_hh_b     = (const float*)d_in[13];
    const float* b_b        = (const float*)d_in[14];
    const float* h2h_W      = (const float*)d_in[15];
    const float* h2h_b      = (const float*)d_in[16];
    const float* gat_Wh     = (const float*)d_in[17];
    const float* gat_ah     = (const float*)d_in[18];
    const float* gat_Wo     = (const float*)d_in[19];
    const float* gat_ao     = (const float*)d_in[20];
    const float* fuse_w     = (const float*)d_in[21];
    const float* trans      = (const float*)d_in[22];

    cudaFuncSetAttribute(attn1_agg_kernel,
                         cudaFuncAttributeMaxDynamicSharedMemorySize, SMEM_ATTN1);

    // xw = emb @ W_ih^T + b  (char-embedding gather fused into A-load)
    {
        dim3 grid(4, 96);
        gemm_kernel<<<grid, 256>>>(0, char_table, batch_char, w_ih_f, b_f,
                                   OFF_XW, BSROWS, 256, ECHAR, 1, 1, 1);
        gemm_kernel<<<grid, 256>>>(0, char_table, batch_char, w_ih_b, b_b,
                                   OFF_XW + BSROWS * 256, BSROWS, 256, ECHAR, 1, 1, 1);
    }
    embed_gaz_kernel<<<(Bb * Gg * Dd + 255) / 256, 256>>>(gaz_list, gaz_table);
    lstm_kernel<<<32, 256>>>(w_hh_f, w_hh_b);

    // lstm projection (lstm rows strided within gatin)
    gemm_kernel<<<dim3(1, 96), 256>>>(OFF_GATIN, nullptr, nullptr, h2h_W, h2h_b,
                                      OFF_LPROJ, BSROWS, Tt, Dd, 1, Ss, NTOK);

    // GAT: projections, smem-cached aggregation, layer-2 GEMM, f1b/f2b, attn2
    gemm_heads_kernel<<<dim3(4, 192, 3), 256>>>(gat_Wh, gat_ah);
    attn1_agg_kernel<<<dim3(2, 64, 3), 256, SMEM_ATTN1>>>(adj0, adj1, adj2);
    for (int z = 0; z < 3; z++)
        gemm_kernel<<<dim3(1, 192), 256>>>(OFF_HCAT + (unsigned)z * BNROWS * 256,
                                           nullptr, nullptr,
                                           gat_Wo + (size_t)z * 256 * Tt, nullptr,
                                           OFF_H2 + (unsigned)z * BNROWS * Tt,
                                           BNROWS, Tt, 256, 0, BNROWS, BNROWS);
    f1f2b_kernel<<<(3 * BNROWS + 7) / 8, 256>>>(gat_ao);
    attn2_kernel<<<dim3(Ss, Bb, 3), 256>>>(adj0, adj1, adj2);

    fuse_kernel<<<(Bb * Ss * Tt + 255) / 256, 256>>>(fuse_w);
    viterbi_kernel<<<Bb, 32>>>(trans, mask, (float*)d_out);
}

// round 11
// speedup vs baseline: 1.4720x; 1.0392x over previous
#include <cuda_runtime.h>
#include <cstdint>
#include <math.h>

// Problem constants
#define Bb     16
#define Ss     384
#define Gg     384
#define NTOK   768
#define ECHAR  100
#define Dd     128
#define Tt     21
#define CSTART 19
#define CSTOP  20
#define BNROWS (Bb*NTOK)    // 12288
#define BSROWS (Bb*Ss)      // 6144

// scratch layout (floats)
#define OFF_XW     0u                       // [2][6144][256]      3,145,728
#define OFF_GATIN  3145728u                 // [12288][128]        1,572,864
#define OFF_HH     4718592u                 // [3][4][12288][64]   9,437,184
#define OFF_F1     14155776u                // [3][4][12288]         147,456
#define OFF_F2     14303232u                //                       147,456
#define OFF_H2     14524416u                // [3][12288][21]        774,144
#define OFF_LPROJ  15298560u                // [6144][21]            129,024
#define OFF_GOUT   15427584u                // [3][6144][21]         387,072
#define OFF_FEATS  15814656u                // [6144][21]            129,024
#define OFF_HCAT   15943680u                // [3][12288][256]     9,437,184
#define SCRATCH_TOTAL 25380864u

__device__ float g_scratch[SCRATCH_TOTAL];

// dynamic smem sizes
#define SMEM_ATTN1 ((49152 + 768) * 4 + 8 * 256 * 8)   // 216,064 B
#define SMEM_ATTN2 (16128 * 4 + 768 * 4 + 8 * 256 * 8) // 84,096 B

__device__ __forceinline__ float fsig(float x) {
    return 1.f / (1.f + __expf(-x));
}
__device__ __forceinline__ float ftanh(float x) {
    x = fminf(15.f, fmaxf(-15.f, x));
    float e = __expf(2.f * x);
    return (e - 1.f) / (e + 1.f);
}

// ---------------- gaz embedding gather ----------------
__global__ void embed_gaz_kernel(const int* __restrict__ gl,
                                 const float* __restrict__ tab) {
    int i = blockIdx.x * blockDim.x + threadIdx.x;
    if (i >= Bb * Gg * Dd) return;
    int r = i / Dd, f = i - r * Dd;
    int b = r / Gg, g = r - b * Gg;
    int idx = gl[r];
    if (idx < 0) idx = 0; if (idx >= 100000) idx = 99999;
    g_scratch[OFF_GATIN + ((size_t)b * NTOK + Ss + g) * Dd + f] =
        tab[(size_t)idx * Dd + f];
}

// ---------------- generic tiled fp32 GEMM (optional gathered-A) ----------------
__global__ __launch_bounds__(256)
void gemm_kernel(unsigned aoff, const float* __restrict__ Aext,
                 const int* __restrict__ gidx,
                 const float* __restrict__ Bm, const float* __restrict__ bias,
                 unsigned coff, int M, int N, int K, int transB,
                 int arpb, int astr) {
    float* C = g_scratch + coff;
    __shared__ __align__(16) float As[16][68];
    __shared__ __align__(16) float Bs[16][68];
    int tid = threadIdx.x;
    int tx = tid & 15, ty = tid >> 4;
    int rowBase = blockIdx.y * 64;
    int colBase = blockIdx.x * 64;
    float acc[4][4] = {};
    for (int k0 = 0; k0 < K; k0 += 16) {
        for (int l = tid; l < 1024; l += 256) {
            int r = l >> 4, kk = l & 15;
            int gr = rowBase + r, gk = k0 + kk;
            float v = 0.f;
            if (gr < M && gk < K) {
                if (gidx) {
                    int ci = gidx[gr];
                    if (ci < 0) ci = 0; if (ci >= 8000) ci = 7999;
                    v = Aext[(size_t)ci * K + gk];
                } else {
                    int sr = (gr / arpb) * astr + (gr % arpb);
                    v = g_scratch[aoff + (size_t)sr * K + gk];
                }
            }
            As[kk][r] = v;
        }
        for (int l = tid; l < 1024; l += 256) {
            int kk = l >> 6, c = l & 63;
            int gk = k0 + kk, gc = colBase + c;
            float v = 0.f;
            if (gk < K && gc < N)
                v = transB ? Bm[(size_t)gc * K + gk] : Bm[(size_t)gk * N + gc];
            Bs[kk][c] = v;
        }
        __syncthreads();
        #pragma unroll
        for (int kk = 0; kk < 16; kk++) {
            float4 av = *(const float4*)&As[kk][ty * 4];
            float4 bv = *(const float4*)&Bs[kk][tx * 4];
            float a[4] = {av.x, av.y, av.z, av.w};
            float b[4] = {bv.x, bv.y, bv.z, bv.w};
            #pragma unroll
            for (int i = 0; i < 4; i++)
                #pragma unroll
                for (int j = 0; j < 4; j++)
                    acc[i][j] += a[i] * b[j];
        }
        __syncthreads();
    }
    #pragma unroll
    for (int i = 0; i < 4; i++) {
        int row = rowBase + ty * 4 + i;
        if (row >= M) continue;
        #pragma unroll
        for (int j = 0; j < 4; j++) {
            int col = colBase + tx * 4 + j;
            if (col >= N) continue;
            float v = acc[i][j];
            if (bias) v += bias[col];
            C[(size_t)row * N + col] = v;
        }
    }
}

// ---------------- h2 projection GEMM: hcat[z] @ Wo[z] for all 3 z ----------------
__global__ __launch_bounds__(256)
void gemm_h2_kernel(const float* __restrict__ WoAll) {
    int z = blockIdx.z;
    const float* A = g_scratch + OFF_HCAT + (size_t)z * BNROWS * 256;
    const float* B = WoAll + (size_t)z * 256 * Tt;
    float* C = g_scratch + OFF_H2 + (size_t)z * BNROWS * Tt;
    __shared__ __align__(16) float As[16][68];
    __shared__ __align__(16) float Bs[16][68];
    int tid = threadIdx.x;
    int tx = tid & 15, ty = tid >> 4;
    int rowBase = blockIdx.y * 64;
    float acc[4][4] = {};
    for (int k0 = 0; k0 < 256; k0 += 16) {
        for (int l = tid; l < 1024; l += 256) {
            int r = l >> 4, kk = l & 15;
            As[kk][r] = A[(size_t)(rowBase + r) * 256 + k0 + kk];
        }
        for (int l = tid; l < 1024; l += 256) {
            int kk = l >> 6, c = l & 63;
            Bs[kk][c] = (c < Tt) ? B[(size_t)(k0 + kk) * Tt + c] : 0.f;
        }
        __syncthreads();
        #pragma unroll
        for (int kk = 0; kk < 16; kk++) {
            float4 av = *(const float4*)&As[kk][ty * 4];
            float4 bv = *(const float4*)&Bs[kk][tx * 4];
            float a[4] = {av.x, av.y, av.z, av.w};
            float b[4] = {bv.x, bv.y, bv.z, bv.w};
            #pragma unroll
            for (int i = 0; i < 4; i++)
                #pragma unroll
                for (int j = 0; j < 4; j++)
                    acc[i][j] += a[i] * b[j];
        }
        __syncthreads();
    }
    #pragma unroll
    for (int i = 0; i < 4; i++) {
        int row = rowBase + ty * 4 + i;
        #pragma unroll
        for (int j = 0; j < 4; j++) {
            int col = tx * 4 + j;
            if (col < Tt)
                C[(size_t)row * Tt + col] = acc[i][j];
        }
    }
}

// ---------------- head-projection GEMM with fused f1/f2 epilogue ----------------
__global__ __launch_bounds__(256)
void gemm_heads_kernel(const float* __restrict__ WhAll, const float* __restrict__ ahAll) {
    int m = blockIdx.x, z = blockIdx.z;
    int hm = z * 4 + m;
    int rowBase = blockIdx.y * 64;
    const float* A = g_scratch + OFF_GATIN;
    const float* B = WhAll + (size_t)hm * (Dd * 64);
    float* C = g_scratch + OFF_HH + (size_t)hm * BNROWS * 64;
    __shared__ __align__(16) float As[16][68];
    __shared__ __align__(16) float Bs[16][68];
    int tid = threadIdx.x;
    int tx = tid & 15, ty = tid >> 4;
    float acc[4][4] = {};
    for (int k0 = 0; k0 < Dd; k0 += 16) {
        for (int l = tid; l < 1024; l += 256) {
            int r = l >> 4, kk = l & 15;
            As[kk][r] = A[(size_t)(rowBase + r) * Dd + k0 + kk];
        }
        for (int l = tid; l < 1024; l += 256) {
            int kk = l >> 6, c = l & 63;
            Bs[kk][c] = B[(size_t)(k0 + kk) * 64 + c];
        }
        __syncthreads();
        #pragma unroll
        for (int kk = 0; kk < 16; kk++) {
            float4 av = *(const float4*)&As[kk][ty * 4];
            float4 bv = *(const float4*)&Bs[kk][tx * 4];
            float a[4] = {av.x, av.y, av.z, av.w};
            float b[4] = {bv.x, bv.y, bv.z, bv.w};
            #pragma unroll
            for (int i = 0; i < 4; i++)
                #pragma unroll
                for (int j = 0; j < 4; j++)
                    acc[i][j] += a[i] * b[j];
        }
        __syncthreads();
    }
    const float* a1 = ahAll + (size_t)hm * 128;
    float av1[4], av2[4];
    #pragma unroll
    for (int j = 0; j < 4; j++) {
        av1[j] = a1[tx * 4 + j];
        av2[j] = a1[64 + tx * 4 + j];
    }
    #pragma unroll
    for (int i = 0; i < 4; i++) {
        int row = rowBase + ty * 4 + i;
        float p1 = 0.f, p2 = 0.f;
        float4 cv;
        cv.x = acc[i][0]; cv.y = acc[i][1]; cv.z = acc[i][2]; cv.w = acc[i][3];
        *(float4*)&C[(size_t)row * 64 + tx * 4] = cv;
        #pragma unroll
        for (int j = 0; j < 4; j++) {
            p1 += acc[i][j] * av1[j];
            p2 += acc[i][j] * av2[j];
        }
        #pragma unroll
        for (int off = 8; off > 0; off >>= 1) {
            p1 += __shfl_xor_sync(0xffffffffu, p1, off);
            p2 += __shfl_xor_sync(0xffffffffu, p2, off);
        }
        if (tx == 0) {
            g_scratch[OFF_F1 + (size_t)hm * BNROWS + row] = p1;
            g_scratch[OFF_F2 + (size_t)hm * BNROWS + row] = p2;
        }
    }
}

// ---------------- BiLSTM (fast transcendentals) ----------------
__global__ __launch_bounds__(256)
void lstm_kernel(const float* __restrict__ whh_f, const float* __restrict__ whh_b) {
    int dir = blockIdx.x & 1, b = blockIdx.x >> 1;
    const float* whh = dir ? whh_b : whh_f;
    int g = threadIdx.x;
    float w[64];
    #pragma unroll
    for (int j = 0; j < 64; j++) w[j] = whh[g * 64 + j];
    __shared__ __align__(16) float hsh[64];
    __shared__ float gates[256];
    float creg = 0.f;
    if (g < 64) hsh[g] = 0.f;
    __syncthreads();
    const float* xwd = g_scratch + OFF_XW + (size_t)dir * BSROWS * 256
                       + (size_t)b * Ss * 256;
    float* gat_in = g_scratch + OFF_GATIN;
    int t = dir ? (Ss - 1) : 0;
    int dt = dir ? -1 : 1;
    bool iscell = (g >= 128 && g < 192);
    float xnext = xwd[(size_t)t * 256 + g];
    for (int step = 0; step < Ss; step++, t += dt) {
        float acc = xnext;
        if (step + 1 < Ss) xnext = xwd[(size_t)(t + dt) * 256 + g];
        const float4* h4 = (const float4*)hsh;
        float a0 = 0.f, a1 = 0.f, a2 = 0.f, a3 = 0.f;
        #pragma unroll
        for (int j4 = 0; j4 < 16; j4++) {
            float4 hv = h4[j4];
            a0 += hv.x * w[4 * j4];
            a1 += hv.y * w[4 * j4 + 1];
            a2 += hv.z * w[4 * j4 + 2];
            a3 += hv.w * w[4 * j4 + 3];
        }
        acc += (a0 + a1) + (a2 + a3);
        gates[g] = iscell ? ftanh(acc) : fsig(acc);
        __syncthreads();
        if (g < 64) {
            creg = gates[64 + g] * creg + gates[g] * gates[128 + g];
            float h = gates[192 + g] * ftanh(creg);
            hsh[g] = h;
            gat_in[((size_t)b * NTOK + t) * Dd + dir * 64 + g] = h;
        }
        __syncthreads();
    }
}

// ---------------- GAT layer-1 aggregation: h panel in smem, warp-per-row ----------------
__global__ __launch_bounds__(256)
void attn1_agg_kernel(const int* __restrict__ adj0, const int* __restrict__ adj1,
                      const int* __restrict__ adj2) {
    extern __shared__ __align__(16) float smem[];
    float* hsm = smem;                           // 49152 floats
    float* f2s = smem + 49152;                   // 768
    float2* psj = (float2*)(smem + 49152 + 768); // 8 warps x 256
    int z = blockIdx.z;
    int m = blockIdx.y >> 4, b = blockIdx.y & 15;
    int chunk = blockIdx.x;
    const int* adj = (z == 0) ? adj0 : (z == 1) ? adj1 : adj2;
    int hm = z * 4 + m;
    int tid = threadIdx.x, lane = tid & 31, w = tid >> 5;

    const float4* hsrc = (const float4*)(g_scratch + OFF_HH
                         + ((size_t)hm * BNROWS + (size_t)b * 768) * 64);
    float4* hdst = (float4*)hsm;
    for (int l = tid; l < 12288; l += 256) hdst[l] = hsrc[l];
    const float* f2g = g_scratch + OFF_F2 + (size_t)hm * BNROWS + (size_t)b * 768;
    for (int l = tid; l < 768; l += 256) f2s[l] = f2g[l];
    __syncthreads();

    float2* mypsj = psj + w * 256;
    const float* f1g = g_scratch + OFF_F1 + (size_t)hm * BNROWS + (size_t)b * 768;
    float* hcat = g_scratch + OFF_HCAT + (size_t)z * BNROWS * 256;
    const float2* h2p = (const float2*)hsm;

    for (int i = chunk * 384 + w; i < chunk * 384 + 384; i += 8) {
        const int4* arow = (const int4*)(adj + ((size_t)b * 768 + i) * 768 + lane * 24);
        int4 a[6];
        #pragma unroll
        for (int q = 0; q < 6; q++) a[q] = arow[q];
        int c = 0;
        #pragma unroll
        for (int q = 0; q < 6; q++)
            c += (a[q].x > 0) + (a[q].y > 0) + (a[q].z > 0) + (a[q].w > 0);
        int pos = c;
        #pragma unroll
        for (int off = 1; off < 32; off <<= 1) {
            int n = __shfl_up_sync(0xffffffffu, pos, off);
            if (lane >= off) pos += n;
        }
        int nnz = __shfl_sync(0xffffffffu, pos, 31);
        pos -= c;
        float f1i = f1g[i];
        int jbase = lane * 24;
        #pragma unroll
        for (int q = 0; q < 6; q++) {
            int vals[4] = {a[q].x, a[q].y, a[q].z, a[q].w};
            #pragma unroll
            for (int r = 0; r < 4; r++) {
                if (vals[r] > 0) {
                    int j = jbase + q * 4 + r;
                    float e = f1i + f2s[j];
                    e = e > 0.f ? e : 0.2f * e;
                    mypsj[pos] = make_float2(e, __int_as_float(j));
                    pos++;
                }
            }
        }
        __syncwarp();
        float mx = -3e38f;
        for (int idx = lane; idx < nnz; idx += 32) mx = fmaxf(mx, mypsj[idx].x);
        #pragma unroll
        for (int off = 16; off > 0; off >>= 1)
            mx = fmaxf(mx, __shfl_xor_sync(0xffffffffu, mx, off));
        float sm = 0.f;
        for (int idx = lane; idx < nnz; idx += 32) {
            float p = expf(mypsj[idx].x - mx);
            mypsj[idx].x = p;
            sm += p;
        }
        #pragma unroll
        for (int off = 16; off > 0; off >>= 1)
            sm += __shfl_xor_sync(0xffffffffu, sm, off);
        __syncwarp();
        float2 acc = make_float2(0.f, 0.f);
        for (int idx = 0; idx < nnz; idx++) {
            float2 pj = mypsj[idx];
            int j = __float_as_int(pj.y);
            float2 hv = h2p[j * 32 + lane];
            acc.x += pj.x * hv.x;
            acc.y += pj.x * hv.y;
        }
        acc.x /= sm;
        acc.y /= sm;
        acc.x = acc.x > 0.f ? acc.x : expm1f(acc.x);
        acc.y = acc.y > 0.f ? acc.y : expm1f(acc.y);
        ((float2*)(hcat + ((size_t)b * 768 + i) * 256 + m * 64))[lane] = acc;
        __syncwarp();
    }
}

// ---------------- GAT layer-2: h2 panel in smem, warp-per-row, fused f1b/f2b ----------------
// grid (16 b, 3 z); block 256; dyn smem SMEM_ATTN2.
__global__ __launch_bounds__(256)
void attn2_panel_kernel(const int* __restrict__ adj0, const int* __restrict__ adj1,
                        const int* __restrict__ adj2,
                        const float* __restrict__ aoAll) {
    extern __shared__ __align__(16) float smem[];
    float* h2sm = smem;                            // 768*21 = 16128
    float* f2s = smem + 16128;                     // 768
    float2* psj = (float2*)(smem + 16128 + 768);   // 8 warps x 256
    int b = blockIdx.x, z = blockIdx.y;
    const int* adj = (z == 0) ? adj0 : (z == 1) ? adj1 : adj2;
    const float* ao = aoAll + (size_t)z * 42;
    const float* h2g = g_scratch + OFF_H2 + ((size_t)z * BNROWS + (size_t)b * 768) * 21;
    int tid = threadIdx.x, lane = tid & 31, w = tid >> 5;

    for (int l = tid; l < 16128; l += 256) h2sm[l] = h2g[l];
    __syncthreads();
    // f2b for all 768 rows
    for (int j = tid; j < 768; j += 256) {
        float s = 0.f;
        #pragma unroll
        for (int t = 0; t < 21; t++) s += h2sm[j * 21 + t] * ao[21 + t];
        f2s[j] = s;
    }
    __syncthreads();

    float2* mypsj = psj + w * 256;
    float* gout = g_scratch + OFF_GOUT + (size_t)z * BSROWS * Tt;
    float ao1 = (lane < 21) ? ao[lane] : 0.f;

    for (int i = w; i < Ss; i += 8) {
        // f1b for row i
        float f1i = (lane < 21) ? h2sm[i * 21 + lane] * ao1 : 0.f;
        #pragma unroll
        for (int off = 16; off > 0; off >>= 1)
            f1i += __shfl_xor_sync(0xffffffffu, f1i, off);
        // adjacency row
        const int4* arow = (const int4*)(adj + ((size_t)b * 768 + i) * 768 + lane * 24);
        int4 a[6];
        #pragma unroll
        for (int q = 0; q < 6; q++) a[q] = arow[q];
        int c = 0;
        #pragma unroll
        for (int q = 0; q < 6; q++)
            c += (a[q].x > 0) + (a[q].y > 0) + (a[q].z > 0) + (a[q].w > 0);
        int pos = c;
        #pragma unroll
        for (int off = 1; off < 32; off <<= 1) {
            int n = __shfl_up_sync(0xffffffffu, pos, off);
            if (lane >= off) pos += n;
        }
        int nnz = __shfl_sync(0xffffffffu, pos, 31);
        pos -= c;
        int jbase = lane * 24;
        #pragma unroll
        for (int q = 0; q < 6; q++) {
            int vals[4] = {a[q].x, a[q].y, a[q].z, a[q].w};
            #pragma unroll
            for (int r = 0; r < 4; r++) {
                if (vals[r] > 0) {
                    int j = jbase + q * 4 + r;
                    float e = f1i + f2s[j];
                    e = e > 0.f ? e : 0.2f * e;
                    mypsj[pos] = make_float2(e, __int_as_float(j));
                    pos++;
                }
            }
        }
        __syncwarp();
        float mx = -3e38f;
        for (int idx = lane; idx < nnz; idx += 32) mx = fmaxf(mx, mypsj[idx].x);
        #pragma unroll
        for (int off = 16; off > 0; off >>= 1)
            mx = fmaxf(mx, __shfl_xor_sync(0xffffffffu, mx, off));
        float sm = 0.f;
        for (int idx = lane; idx < nnz; idx += 32) {
            float p = expf(mypsj[idx].x - mx);
            mypsj[idx].x = p;
            sm += p;
        }
        #pragma unroll
        for (int off = 16; off > 0; off >>= 1)
            sm += __shfl_xor_sync(0xffffffffu, sm, off);
        __syncwarp();
        if (lane < 21) {
            float acc = 0.f;
            for (int idx = 0; idx < nnz; idx++) {
                float2 pj = mypsj[idx];
                int j = __float_as_int(pj.y);
                acc += pj.x * h2sm[j * 21 + lane];
            }
            acc /= sm;
            acc = acc > 0.f ? acc : expm1f(acc);
            gout[((size_t)b * Ss + i) * 21 + lane] = acc;
        }
        __syncwarp();
    }
}

// ---------------- fuse ----------------
__global__ void fuse_kernel(const float* __restrict__ fw) {
    int i = blockIdx.x * blockDim.x + threadIdx.x;
    if (i >= Bb * Ss * Tt) return;
    const float* lproj = g_scratch + OFF_LPROJ;
    const float* g0 = g_scratch + OFF_GOUT;
    const float* g1 = g0 + BSROWS * Tt;
    const float* g2 = g1 + BSROWS * Tt;
    g_scratch[OFF_FEATS + i] =
        fw[0] * lproj[i] + fw[1] * g0[i] + fw[2] * g1[i] + fw[3] * g2[i];
}

// ---------------- Viterbi (float32 output) ----------------
__global__ __launch_bounds__(32)
void viterbi_kernel(const float* __restrict__ trans,
                    const int* __restrict__ mask, float* __restrict__ outv) {
    const float* feats = g_scratch + OFF_FEATS;
    int b = blockIdx.x;
    int tid = threadIdx.x;
    __shared__ float part[21], np[21];
    __shared__ float trsh[441];
    __shared__ short bps[Ss * Tt];
    __shared__ int tags[Ss];
    for (int l = tid; l < 441; l += 32) trsh[l] = trans[l];
    __syncthreads();
    if (tid < 21)
        part[tid] = feats[((size_t)b * Ss) * Tt + tid] + trsh[CSTART * 21 + tid];
    __syncthreads();
    for (int t = 1; t < Ss; t++) {
        if (tid < 21) {
            float ft = feats[((size_t)b * Ss + t) * Tt + tid];
            float best = -3e38f; int bi = 0;
            #pragma unroll
            for (int p = 0; p < 21; p++) {
                float v = part[p] + trsh[p * 21 + tid] + ft;
                if (v > best) { best = v; bi = p; }
            }
            int m = mask[b * Ss + t];
            np[tid] = (m > 0) ? best : part[tid];
            bps[t * Tt + tid] = (short)((m > 0) ? bi : tid);
        }
        __syncthreads();
        if (tid < 21) part[tid] = np[tid];
        __syncthreads();
    }
    if (tid == 0) {
        float best = -3e38f; int bt = 0;
        for (int p = 0; p < 21; p++) {
            float v = part[p] + trsh[p * 21 + CSTOP];
            if (v > best) { best = v; bt = p; }
        }
        tags[Ss - 1] = bt;
        int tag = bt;
        for (int t = Ss - 1; t >= 1; t--) {
            tag = (int)bps[t * Tt + tag];
            tags[t - 1] = tag;
        }
    }
    __syncthreads();
    for (int t = tid; t < Ss; t += 32)
        outv[(size_t)b * Ss + t] = (float)tags[t];
}

// ---------------- launch ----------------
extern "C" void kernel_launch(void* const* d_in, const int* in_sizes, int n_in,
                              void* d_out, int out_size) {
    const int*   batch_char = (const int*)d_in[0];
    const int*   gaz_list   = (const int*)d_in[2];
    const int*   adj0       = (const int*)d_in[3];
    const int*   adj1       = (const int*)d_in[4];
    const int*   adj2       = (const int*)d_in[5];
    const int*   mask       = (const int*)d_in[6];
    const float* char_table = (const float*)d_in[7];
    const float* gaz_table  = (const float*)d_in[8];
    const float* w_ih_f     = (const float*)d_in[9];
    const float* w_hh_f     = (const float*)d_in[10];
    const float* b_f        = (const float*)d_in[11];
    const float* w_ih_b     = (const float*)d_in[12];
    const float* w_hh_b     = (const float*)d_in[13];
    const float* b_b        = (const float*)d_in[14];
    const float* h2h_W      = (const float*)d_in[15];
    const float* h2h_b      = (const float*)d_in[16];
    const float* gat_Wh     = (const float*)d_in[17];
    const float* gat_ah     = (const float*)d_in[18];
    const float* gat_Wo     = (const float*)d_in[19];
    const float* gat_ao     = (const float*)d_in[20];
    const float* fuse_w     = (const float*)d_in[21];
    const float* trans      = (const float*)d_in[22];

    cudaFuncSetAttribute(attn1_agg_kernel,
                         cudaFuncAttributeMaxDynamicSharedMemorySize, SMEM_ATTN1);
    cudaFuncSetAttribute(attn2_panel_kernel,
                         cudaFuncAttributeMaxDynamicSharedMemorySize, SMEM_ATTN2);

    // xw = emb @ W_ih^T + b  (char-embedding gather fused into A-load)
    {
        dim3 grid(4, 96);
        gemm_kernel<<<grid, 256>>>(0, char_table, batch_char, w_ih_f, b_f,
                                   OFF_XW, BSROWS, 256, ECHAR, 1, 1, 1);
        gemm_kernel<<<grid, 256>>>(0, char_table, batch_char, w_ih_b, b_b,
                                   OFF_XW + BSROWS * 256, BSROWS, 256, ECHAR, 1, 1, 1);
    }
    embed_gaz_kernel<<<(Bb * Gg * Dd + 255) / 256, 256>>>(gaz_list, gaz_table);
    lstm_kernel<<<32, 256>>>(w_hh_f, w_hh_b);

    // lstm projection (lstm rows strided within gatin)
    gemm_kernel<<<dim3(1, 96), 256>>>(OFF_GATIN, nullptr, nullptr, h2h_W, h2h_b,
                                      OFF_LPROJ, BSROWS, Tt, Dd, 1, Ss, NTOK);

    // GAT pipeline
    gemm_heads_kernel<<<dim3(4, 192, 3), 256>>>(gat_Wh, gat_ah);
    attn1_agg_kernel<<<dim3(2, 64, 3), 256, SMEM_ATTN1>>>(adj0, adj1, adj2);
    gemm_h2_kernel<<<dim3(1, 192, 3), 256>>>(gat_Wo);
    attn2_panel_kernel<<<dim3(Bb, 3), 256, SMEM_ATTN2>>>(adj0, adj1, adj2, gat_ao);

    fuse_kernel<<<(Bb * Ss * Tt + 255) / 256, 256>>>(fuse_w);
    viterbi_kernel<<<Bb, 32>>>(trans, mask, (float*)d_out);
}